// round 13
// baseline (speedup 1.0000x reference)
#include <cuda_runtime.h>
#include <cuda_fp16.h>

#define BB 4
#define SS 2048
#define DD 768
#define HH 8
#define DHH 96
#define MM (BB*SS)   // 8192

// Pure fp16 scratch (fp32 accumulate in mma)
__device__ __half g_Xqh[(size_t)MM*DD];
__device__ __half g_Xkh[(size_t)MM*DD];
__device__ __half g_Xvh[(size_t)MM*DD];
__device__ __half g_Wqh[(size_t)HH*DD*DHH];
__device__ __half g_Wkh[(size_t)HH*DD*DHH];
__device__ __half g_Wvh[(size_t)HH*DD*DHH];
__device__ __half g_Woh[(size_t)DD*DD];
__device__ __half g_Qh[(size_t)BB*HH*SS*DHH];   // pre-scaled by log2e/sqrt(96)
__device__ __half g_Kh[(size_t)BB*HH*SS*DHH];
__device__ __half g_Vh[(size_t)BB*HH*SS*DHH];
__device__ __half g_cath[(size_t)MM*DD];

__device__ __forceinline__ unsigned su32(const void* p) {
    return (unsigned)__cvta_generic_to_shared(p);
}
// packed fp32x2 -> fp16x2 convert (1 instr instead of 2 cvt + pack)
__device__ __forceinline__ unsigned cvt2h(float lo, float hi) {
    unsigned r;
    asm("cvt.rn.f16x2.f32 %0, %1, %2;" : "=r"(r) : "f"(hi), "f"(lo));
    return r;
}
__device__ __forceinline__ void ldsm4(unsigned r[4], unsigned addr) {
    asm volatile("ldmatrix.sync.aligned.m8n8.x4.shared.b16 {%0,%1,%2,%3},[%4];\n"
        : "=r"(r[0]), "=r"(r[1]), "=r"(r[2]), "=r"(r[3]) : "r"(addr));
}
__device__ __forceinline__ void ldsm4t(unsigned r[4], unsigned addr) {
    asm volatile("ldmatrix.sync.aligned.m8n8.x4.trans.shared.b16 {%0,%1,%2,%3},[%4];\n"
        : "=r"(r[0]), "=r"(r[1]), "=r"(r[2]), "=r"(r[3]) : "r"(addr));
}
__device__ __forceinline__ void mma16816(float* c, const unsigned* a, const unsigned* b) {
    asm volatile("mma.sync.aligned.m16n8k16.row.col.f32.f16.f16.f32 "
        "{%0,%1,%2,%3},{%4,%5,%6,%7},{%8,%9},{%0,%1,%2,%3};\n"
        : "+f"(c[0]), "+f"(c[1]), "+f"(c[2]), "+f"(c[3])
        : "r"(a[0]), "r"(a[1]), "r"(a[2]), "r"(a[3]), "r"(b[0]), "r"(b[1]));
}
#define CPA(dst, src) asm volatile("cp.async.cg.shared.global [%0], [%1], 16;\n" :: "r"(dst), "l"(src))
#define CP_COMMIT asm volatile("cp.async.commit_group;\n")
#define CP_WAIT2  asm volatile("cp.async.wait_group 2;\n")
#define CP_WAIT1  asm volatile("cp.async.wait_group 1;\n")
#define CP_WAIT0  asm volatile("cp.async.wait_group 0;\n")

// ---------------------------------------------------------------------------
// Preconvert fp32 -> fp16 (all 7 tensors, one launch)
// ---------------------------------------------------------------------------
#define NX4 (MM*DD/4)          // 1572864
#define NW4 (HH*DD*DHH/4)      // 147456

__global__ __launch_bounds__(256) void convert_all(
    const float* __restrict__ Xq, const float* __restrict__ Xk, const float* __restrict__ Xv,
    const float* __restrict__ Wq, const float* __restrict__ Wk, const float* __restrict__ Wv,
    const float* __restrict__ Wo)
{
    int i = blockIdx.x * 256 + threadIdx.x;
    const float* src; __half* dh; int off;
    if (i < 3 * NX4) {
        int t = i / NX4; off = i - t * NX4;
        src = (t == 0) ? Xq : (t == 1) ? Xk : Xv;
        dh  = (t == 0) ? g_Xqh : (t == 1) ? g_Xkh : g_Xvh;
    } else {
        int j = i - 3 * NX4;
        if (j >= 4 * NW4) return;
        int t = j / NW4; off = j - t * NW4;
        src = (t == 0) ? Wq : (t == 1) ? Wk : (t == 2) ? Wv : Wo;
        dh  = (t == 0) ? g_Wqh : (t == 1) ? g_Wkh : (t == 2) ? g_Wvh : g_Woh;
    }
    float4 v = ((const float4*)src)[off];
    uint2 u;
    u.x = cvt2h(v.x, v.y);
    u.y = cvt2h(v.z, v.w);
    ((uint2*)dh)[off] = u;
}

// ---------------------------------------------------------------------------
// QKV GEMM (fp16, fp32 accum). BM=128, BN=96, BK=64, 2-stage cp.async.
// Q pre-scaled by log2e/sqrt(96) (softmax runs in base-2). grid=(64, 8, 3).
// ---------------------------------------------------------------------------
#define QK_LDA 72
#define QK_LDB 104

__device__ __forceinline__ void qkv_load(
    __half* Ah, __half* Bh,
    const __half* gXh, const __half* gWh,
    int p, int m0, int kt, size_t wbase, int tid)
{
    #pragma unroll
    for (int j = 0; j < 7; j++) {
        int c = tid + j * 256;             // 0..1791
        if (c < 1024) {
            int row = c >> 3, off = (c & 7) * 8;
            CPA(su32(Ah + p * (128*QK_LDA) + row * QK_LDA + off),
                gXh + (size_t)(m0 + row) * DD + kt + off);
        } else {
            int c2 = c - 1024;             // 0..767
            int row = c2 / 12, off = (c2 - row * 12) * 8;
            CPA(su32(Bh + p * (64*QK_LDB) + row * QK_LDB + off),
                gWh + wbase + (size_t)(kt + row) * DHH + off);
        }
    }
}

__global__ __launch_bounds__(256, 2) void qkv_kernel(
    const float* __restrict__ bq, const float* __restrict__ bk, const float* __restrict__ bv)
{
    extern __shared__ __half smq[];
    __half* Ah = smq;                      // 2 x 128 x 72
    __half* Bh = Ah + 2*128*QK_LDA;        // 2 x 64 x 104

    const __half *gXh, *gWh; const float* bias; __half *oh;
    if (blockIdx.z == 0)      { gXh=g_Xqh; gWh=g_Wqh; bias=bq; oh=g_Qh; }
    else if (blockIdx.z == 1) { gXh=g_Xkh; gWh=g_Wkh; bias=bk; oh=g_Kh; }
    else                      { gXh=g_Xvh; gWh=g_Wvh; bias=bv; oh=g_Vh; }
    // Q carries softmax scale AND log2(e) so attention can use exp2
    const float oscale = (blockIdx.z == 0) ? rsqrtf(96.0f) * 1.4426950408889634f : 1.0f;

    const int h   = blockIdx.y;
    const int m0  = blockIdx.x * 128;
    const int tid = threadIdx.x;
    const int wid = tid >> 5, lane = tid & 31;
    const int wm  = wid >> 1, wn = wid & 1;
    const size_t wbase = (size_t)h * DD * DHH;

    float acc[2][6][4];
    #pragma unroll
    for (int i = 0; i < 2; i++)
        #pragma unroll
        for (int j = 0; j < 6; j++)
            #pragma unroll
            for (int k = 0; k < 4; k++) acc[i][j][k] = 0.f;

    const int lrow = lane & 15, lcol8 = (lane >> 4) << 3;

    qkv_load(Ah, Bh, gXh, gWh, 0, m0, 0, wbase, tid);
    CP_COMMIT;

    const int NT = DD / 64;   // 12
    for (int it = 0; it < NT; it++) {
        int p = it & 1;
        if (it + 1 < NT) {
            qkv_load(Ah, Bh, gXh, gWh, (it+1)&1, m0, (it+1)*64, wbase, tid);
            CP_COMMIT;
            CP_WAIT1;
        } else {
            CP_WAIT0;
        }
        __syncthreads();

        __half* Ahp = Ah + p * (128*QK_LDA);
        __half* Bhp = Bh + p * (64*QK_LDB);

        #pragma unroll
        for (int ks = 0; ks < 4; ks++) {
            int k0 = ks * 16;
            unsigned ah[2][4];
            #pragma unroll
            for (int mf = 0; mf < 2; mf++) {
                int row = wm * 32 + mf * 16 + lrow;
                ldsm4(ah[mf], su32(Ahp + row * QK_LDA + k0 + lcol8));
            }
            #pragma unroll
            for (int nf2 = 0; nf2 < 3; nf2++) {
                unsigned bh[4];
                int n0 = wn * 48 + nf2 * 16;
                ldsm4t(bh, su32(Bhp + (k0 + lrow) * QK_LDB + n0 + lcol8));
                #pragma unroll
                for (int hn = 0; hn < 2; hn++) {
                    #pragma unroll
                    for (int mf = 0; mf < 2; mf++)
                        mma16816(acc[mf][nf2*2 + hn], ah[mf], bh + hn*2);
                }
            }
        }
        __syncthreads();
    }

    #pragma unroll
    for (int mf = 0; mf < 2; mf++) {
        #pragma unroll
        for (int nf = 0; nf < 6; nf++) {
            int col = wn * 48 + nf * 8 + (lane & 3) * 2;
            float b0 = bias[h*DHH + col], b1 = bias[h*DHH + col + 1];
            #pragma unroll
            for (int hr = 0; hr < 2; hr++) {
                int m = m0 + wm * 32 + mf * 16 + (lane >> 2) + hr * 8;
                int bb = m >> 11, s = m & 2047;
                size_t off = (((size_t)(bb * HH + h)) * SS + s) * DHH + col;
                float v0 = (acc[mf][nf][hr*2 + 0] + b0) * oscale;
                float v1 = (acc[mf][nf][hr*2 + 1] + b1) * oscale;
                *(unsigned*)(oh + off) = cvt2h(v0, v1);
            }
        }
    }
}

// ---------------------------------------------------------------------------
// Flash attention, fp16 mma, 3-region KV pipeline (Q region reused as stage).
// Softmax in base-2 (Q pre-scaled by log2e): exp2f, no extra FMULs.
// ---------------------------------------------------------------------------
#define AT_LD 104
#define KV_REG (2*64*AT_LD)   // one region = K(64x104) + V(64x104)

__device__ __forceinline__ void attn_load_kv(__half* Kbuf, size_t gbase, int tid)
{
    __half* Vbuf = Kbuf + 64 * AT_LD;
    #pragma unroll
    for (int j = 0; j < 6; j++) {
        int c = tid + j * 256;            // 0..1535
        int arr = (c >= 768) ? 1 : 0;
        int rem = c - arr * 768;
        int row = rem / 12;
        int off = (rem - row * 12) * 8;
        const __half* sp = (arr ? g_Vh : g_Kh) + (gbase + row) * DHH + off;
        __half* dp = (arr ? Vbuf : Kbuf) + row * AT_LD + off;
        CPA(su32(dp), sp);
    }
}

__global__ __launch_bounds__(256, 2) void attn_kernel()
{
    extern __shared__ __half smh[];
    __half* R0 = smh;
    __half* R1 = smh + KV_REG;
    __half* R2 = smh + 2 * KV_REG;

    const int b  = blockIdx.z, h = blockIdx.y;
    const int s0 = blockIdx.x * 128;
    const int tid = threadIdx.x, wid = tid >> 5, lane = tid & 31;
    const size_t base = ((size_t)(b * HH + h)) * SS;

    {   // load Q tile into region 0
        int r = tid >> 1, c0 = (tid & 1) * 48;
        size_t go = (base + s0 + r) * DHH + c0;
        __half* dh = R0 + r * AT_LD + c0;
        #pragma unroll
        for (int i = 0; i < 6; i++)
            *(uint4*)(dh + i*8) = *(const uint4*)(g_Qh + go + i*8);
    }

    attn_load_kv(R1, base, tid);      CP_COMMIT;   // tile 0
    attn_load_kv(R2, base + 64, tid); CP_COMMIT;   // tile 1

    const int lrow = lane & 15, lcol8 = (lane >> 4) << 3;
    const int krow_off = (lane & 7) + ((lane & 16) >> 1);
    const int kcol_off = (lane & 8);

    __syncthreads();   // Q ready
    unsigned qf[6][4];
    {
        int qrow = wid * 16 + lrow;
        #pragma unroll
        for (int dk = 0; dk < 6; dk++)
            ldsm4(qf[dk], su32(R0 + qrow * AT_LD + dk * 16 + lcol8));
    }
    __syncthreads();   // region 0 reusable

    attn_load_kv(R0, base + 128, tid); CP_COMMIT;  // tile 2

    float oacc[12][4];
    #pragma unroll
    for (int j = 0; j < 12; j++)
        #pragma unroll
        for (int t = 0; t < 4; t++) oacc[j][t] = 0.f;
    float m0r = -1e30f, m1r = -1e30f, l0r = 0.f, l1r = 0.f;

    const int NT = SS / 64;   // 32
    int cur = 1;
    for (int it = 0; it < NT; it++) {
        if (it < NT - 2)      { CP_WAIT2; }
        else if (it == NT - 2){ CP_WAIT1; }
        else                  { CP_WAIT0; }
        __syncthreads();

        __half* Kp = smh + cur * KV_REG;
        __half* Vp = Kp + 64 * AT_LD;

        // S = Q @ K^T (scores already in log2 domain)
        float sacc[8][4];
        #pragma unroll
        for (int j = 0; j < 8; j++)
            #pragma unroll
            for (int t = 0; t < 4; t++) sacc[j][t] = 0.f;

        #pragma unroll
        for (int dk = 0; dk < 6; dk++) {
            int d0 = dk * 16;
            #pragma unroll
            for (int nf2 = 0; nf2 < 4; nf2++) {
                unsigned bh[4];
                ldsm4(bh, su32(Kp + (nf2 * 16 + krow_off) * AT_LD + d0 + kcol_off));
                mma16816(sacc[nf2*2 + 0], qf[dk], bh + 0);
                mma16816(sacc[nf2*2 + 1], qf[dk], bh + 2);
            }
        }

        // online softmax (base-2, registers)
        float mx0 = -1e30f, mx1 = -1e30f;
        #pragma unroll
        for (int j = 0; j < 8; j++) {
            mx0 = fmaxf(mx0, fmaxf(sacc[j][0], sacc[j][1]));
            mx1 = fmaxf(mx1, fmaxf(sacc[j][2], sacc[j][3]));
        }
        mx0 = fmaxf(mx0, __shfl_xor_sync(0xffffffffu, mx0, 1));
        mx0 = fmaxf(mx0, __shfl_xor_sync(0xffffffffu, mx0, 2));
        mx1 = fmaxf(mx1, __shfl_xor_sync(0xffffffffu, mx1, 1));
        mx1 = fmaxf(mx1, __shfl_xor_sync(0xffffffffu, mx1, 2));
        float mn0 = fmaxf(m0r, mx0), mn1 = fmaxf(m1r, mx1);
        float corr0 = exp2f(m0r - mn0), corr1 = exp2f(m1r - mn1);
        m0r = mn0; m1r = mn1;
        float sum0 = 0.f, sum1 = 0.f;
        #pragma unroll
        for (int j = 0; j < 8; j++) {
            sacc[j][0] = exp2f(sacc[j][0] - mn0);
            sacc[j][1] = exp2f(sacc[j][1] - mn0);
            sacc[j][2] = exp2f(sacc[j][2] - mn1);
            sacc[j][3] = exp2f(sacc[j][3] - mn1);
            sum0 += sacc[j][0] + sacc[j][1];
            sum1 += sacc[j][2] + sacc[j][3];
        }
        sum0 += __shfl_xor_sync(0xffffffffu, sum0, 1);
        sum0 += __shfl_xor_sync(0xffffffffu, sum0, 2);
        sum1 += __shfl_xor_sync(0xffffffffu, sum1, 1);
        sum1 += __shfl_xor_sync(0xffffffffu, sum1, 2);
        l0r = l0r * corr0 + sum0;
        l1r = l1r * corr1 + sum1;

        #pragma unroll
        for (int j = 0; j < 12; j++) {
            oacc[j][0] *= corr0; oacc[j][1] *= corr0;
            oacc[j][2] *= corr1; oacc[j][3] *= corr1;
        }

        // P fragments (packed cvt)
        unsigned ph[4][4];
        #pragma unroll
        for (int kf = 0; kf < 4; kf++) {
            #pragma unroll
            for (int q = 0; q < 4; q++) {
                int fj = kf*2 + (q >> 1);
                int t0 = (q & 1) * 2;
                ph[kf][q] = cvt2h(sacc[fj][t0], sacc[fj][t0 + 1]);
            }
        }

        // O += P @ V
        #pragma unroll
        for (int kf = 0; kf < 4; kf++) {
            int k0 = kf * 16;
            #pragma unroll
            for (int nf2 = 0; nf2 < 6; nf2++) {
                unsigned bh[4];
                ldsm4t(bh, su32(Vp + (k0 + lrow) * AT_LD + nf2 * 16 + lcol8));
                mma16816(oacc[nf2*2 + 0], ph[kf], bh + 0);
                mma16816(oacc[nf2*2 + 1], ph[kf], bh + 2);
            }
        }
        __syncthreads();
        if (it + 3 < NT) {
            attn_load_kv(Kp, base + (size_t)(it + 3) * 64, tid);
            CP_COMMIT;
        }
        cur = (cur == 2) ? 0 : cur + 1;
    }

    // Epilogue: normalize, store cat (fp16, packed cvt)
    float inv0 = 1.0f / l0r, inv1 = 1.0f / l1r;
    #pragma unroll
    for (int nf = 0; nf < 12; nf++) {
        int col = h * DHH + nf * 8 + (lane & 3) * 2;
        #pragma unroll
        for (int hr = 0; hr < 2; hr++) {
            int s = s0 + wid * 16 + (lane >> 2) + hr * 8;
            size_t off = ((size_t)b * SS + s) * DD + col;
            float inv = hr ? inv1 : inv0;
            *(unsigned*)(g_cath + off) =
                cvt2h(oacc[nf][hr*2 + 0] * inv, oacc[nf][hr*2 + 1] * inv);
        }
    }
}

// ---------------------------------------------------------------------------
// Output projection (fp16): out = cath @ Woh + bo. BM=128, BN=128, BK=64.
// ---------------------------------------------------------------------------
#define OP_LDA 72
#define OP_LDB 136

__device__ __forceinline__ void oproj_load(
    __half* Ah, __half* Bh, int p, int m0, int n0b, int kt, int tid)
{
    #pragma unroll
    for (int j = 0; j < 8; j++) {
        int c = tid + j * 256;             // 0..2047
        if (c < 1024) {
            int row = c >> 3, off = (c & 7) * 8;
            CPA(su32(Ah + p * (128*OP_LDA) + row * OP_LDA + off),
                g_cath + (size_t)(m0 + row) * DD + kt + off);
        } else {
            int c2 = c - 1024;             // 0..1023
            int row = c2 >> 4, off = (c2 & 15) * 8;
            CPA(su32(Bh + p * (64*OP_LDB) + row * OP_LDB + off),
                g_Woh + (size_t)(kt + row) * DD + n0b + off);
        }
    }
}

__global__ __launch_bounds__(256, 2) void oproj_kernel(
    const float* __restrict__ bo, float* __restrict__ out)
{
    extern __shared__ __half smo[];
    __half* Ah = smo;
    __half* Bh = Ah + 2*128*OP_LDA;

    const int m0  = blockIdx.x * 128;
    const int n0b = blockIdx.y * 128;
    const int tid = threadIdx.x, wid = tid >> 5, lane = tid & 31;
    const int wm = wid >> 1, wn = wid & 1;

    float acc[2][8][4];
    #pragma unroll
    for (int i = 0; i < 2; i++)
        #pragma unroll
        for (int j = 0; j < 8; j++)
            #pragma unroll
            for (int k = 0; k < 4; k++) acc[i][j][k] = 0.f;

    const int lrow = lane & 15, lcol8 = (lane >> 4) << 3;

    oproj_load(Ah, Bh, 0, m0, n0b, 0, tid);
    CP_COMMIT;

    const int NT = DD / 64;   // 12
    for (int it = 0; it < NT; it++) {
        int p = it & 1;
        if (it + 1 < NT) {
            oproj_load(Ah, Bh, (it+1)&1, m0, n0b, (it+1)*64, tid);
            CP_COMMIT;
            CP_WAIT1;
        } else {
            CP_WAIT0;
        }
        __syncthreads();

        __half* Ahp = Ah + p * (128*OP_LDA);
        __half* Bhp = Bh + p * (64*OP_LDB);

        #pragma unroll
        for (int ks = 0; ks < 4; ks++) {
            int k0 = ks * 16;
            unsigned ah[2][4];
            #pragma unroll
            for (int mf = 0; mf < 2; mf++) {
                int row = wm * 32 + mf * 16 + lrow;
                ldsm4(ah[mf], su32(Ahp + row * OP_LDA + k0 + lcol8));
            }
            #pragma unroll
            for (int nf2 = 0; nf2 < 4; nf2++) {
                unsigned bh[4];
                int n0 = wn * 64 + nf2 * 16;
                ldsm4t(bh, su32(Bhp + (k0 + lrow) * OP_LDB + n0 + lcol8));
                #pragma unroll
                for (int hn = 0; hn < 2; hn++) {
                    #pragma unroll
                    for (int mf = 0; mf < 2; mf++)
                        mma16816(acc[mf][nf2*2 + hn], ah[mf], bh + hn*2);
                }
            }
        }
        __syncthreads();
    }

    #pragma unroll
    for (int mf = 0; mf < 2; mf++) {
        #pragma unroll
        for (int nf = 0; nf < 8; nf++) {
            int col = n0b + wn * 64 + nf * 8 + (lane & 3) * 2;
            float b0 = bo[col], b1 = bo[col + 1];
            #pragma unroll
            for (int hr = 0; hr < 2; hr++) {
                int m = m0 + wm * 32 + mf * 16 + (lane >> 2) + hr * 8;
                float2 v = make_float2(acc[mf][nf][hr*2+0] + b0,
                                       acc[mf][nf][hr*2+1] + b1);
                *(float2*)(out + (size_t)m * DD + col) = v;
            }
        }
    }
}

// ---------------------------------------------------------------------------
extern "C" void kernel_launch(void* const* d_in, const int* in_sizes, int n_in,
                              void* d_out, int out_size)
{
    (void)in_sizes; (void)n_in; (void)out_size;
    const float* Xq = (const float*)d_in[0];
    const float* Xk = (const float*)d_in[1];
    const float* Xv = (const float*)d_in[2];
    const float* Wq = (const float*)d_in[3];
    const float* bq = (const float*)d_in[4];
    const float* Wk = (const float*)d_in[5];
    const float* bk = (const float*)d_in[6];
    const float* Wv = (const float*)d_in[7];
    const float* bv = (const float*)d_in[8];
    const float* Wo = (const float*)d_in[9];
    const float* bo = (const float*)d_in[10];
    float* out = (float*)d_out;

    const int total4 = 3*NX4 + 4*NW4;
    convert_all<<<(total4 + 255) / 256, 256>>>(Xq, Xk, Xv, Wq, Wk, Wv, Wo);

    const int smem_qkv = (2*128*QK_LDA + 2*64*QK_LDB) * (int)sizeof(__half);   // 63488
    cudaFuncSetAttribute(qkv_kernel, cudaFuncAttributeMaxDynamicSharedMemorySize, smem_qkv);
    dim3 gq(MM / 128, HH, 3);
    qkv_kernel<<<gq, 256, smem_qkv>>>(bq, bk, bv);

    const int smem_attn = 3 * KV_REG * (int)sizeof(__half);                    // 79872
    cudaFuncSetAttribute(attn_kernel, cudaFuncAttributeMaxDynamicSharedMemorySize, smem_attn);
    dim3 ga(SS / 128, HH, BB);
    attn_kernel<<<ga, 256, smem_attn>>>();

    const int smem_op = (2*128*OP_LDA + 2*64*OP_LDB) * (int)sizeof(__half);    // 71680
    cudaFuncSetAttribute(oproj_kernel, cudaFuncAttributeMaxDynamicSharedMemorySize, smem_op);
    dim3 go(MM / 128, DD / 128);
    oproj_kernel<<<go, 256, smem_op>>>(bo, out);
}

// round 14
// speedup vs baseline: 1.4988x; 1.4988x over previous
#include <cuda_runtime.h>
#include <cuda_fp16.h>

#define BB 4
#define SS 2048
#define DD 768
#define HH 8
#define DHH 96
#define MM (BB*SS)   // 8192

// Pure fp16 scratch (fp32 accumulate in mma)
__device__ __half g_Xqh[(size_t)MM*DD];
__device__ __half g_Xkh[(size_t)MM*DD];
__device__ __half g_Xvh[(size_t)MM*DD];
__device__ __half g_Wqh[(size_t)HH*DD*DHH];
__device__ __half g_Wkh[(size_t)HH*DD*DHH];
__device__ __half g_Wvh[(size_t)HH*DD*DHH];
__device__ __half g_Woh[(size_t)DD*DD];
__device__ __half g_Qh[(size_t)BB*HH*SS*DHH];
__device__ __half g_Kh[(size_t)BB*HH*SS*DHH];
__device__ __half g_Vh[(size_t)BB*HH*SS*DHH];
__device__ __half g_cath[(size_t)MM*DD];

__device__ __forceinline__ unsigned su32(const void* p) {
    return (unsigned)__cvta_generic_to_shared(p);
}
__device__ __forceinline__ unsigned h2u(half2 v) {
    union { half2 h; unsigned u; } x; x.h = v; return x.u;
}
__device__ __forceinline__ void ldsm4(unsigned r[4], unsigned addr) {
    asm volatile("ldmatrix.sync.aligned.m8n8.x4.shared.b16 {%0,%1,%2,%3},[%4];\n"
        : "=r"(r[0]), "=r"(r[1]), "=r"(r[2]), "=r"(r[3]) : "r"(addr));
}
__device__ __forceinline__ void ldsm4t(unsigned r[4], unsigned addr) {
    asm volatile("ldmatrix.sync.aligned.m8n8.x4.trans.shared.b16 {%0,%1,%2,%3},[%4];\n"
        : "=r"(r[0]), "=r"(r[1]), "=r"(r[2]), "=r"(r[3]) : "r"(addr));
}
__device__ __forceinline__ void mma16816(float* c, const unsigned* a, const unsigned* b) {
    asm volatile("mma.sync.aligned.m16n8k16.row.col.f32.f16.f16.f32 "
        "{%0,%1,%2,%3},{%4,%5,%6,%7},{%8,%9},{%0,%1,%2,%3};\n"
        : "+f"(c[0]), "+f"(c[1]), "+f"(c[2]), "+f"(c[3])
        : "r"(a[0]), "r"(a[1]), "r"(a[2]), "r"(a[3]), "r"(b[0]), "r"(b[1]));
}
#define CPA(dst, src) asm volatile("cp.async.cg.shared.global [%0], [%1], 16;\n" :: "r"(dst), "l"(src))
#define CP_COMMIT asm volatile("cp.async.commit_group;\n")
#define CP_WAIT2  asm volatile("cp.async.wait_group 2;\n")
#define CP_WAIT1  asm volatile("cp.async.wait_group 1;\n")
#define CP_WAIT0  asm volatile("cp.async.wait_group 0;\n")

// ---------------------------------------------------------------------------
// Preconvert fp32 -> fp16 (all 7 tensors, one launch)
// ---------------------------------------------------------------------------
#define NX4 (MM*DD/4)          // 1572864
#define NW4 (HH*DD*DHH/4)      // 147456

__global__ __launch_bounds__(256) void convert_all(
    const float* __restrict__ Xq, const float* __restrict__ Xk, const float* __restrict__ Xv,
    const float* __restrict__ Wq, const float* __restrict__ Wk, const float* __restrict__ Wv,
    const float* __restrict__ Wo)
{
    int i = blockIdx.x * 256 + threadIdx.x;
    const float* src; __half* dh; int off;
    if (i < 3 * NX4) {
        int t = i / NX4; off = i - t * NX4;
        src = (t == 0) ? Xq : (t == 1) ? Xk : Xv;
        dh  = (t == 0) ? g_Xqh : (t == 1) ? g_Xkh : g_Xvh;
    } else {
        int j = i - 3 * NX4;
        if (j >= 4 * NW4) return;
        int t = j / NW4; off = j - t * NW4;
        src = (t == 0) ? Wq : (t == 1) ? Wk : (t == 2) ? Wv : Wo;
        dh  = (t == 0) ? g_Wqh : (t == 1) ? g_Wkh : (t == 2) ? g_Wvh : g_Woh;
    }
    float4 v = ((const float4*)src)[off];
    union { __half h[4]; uint2 u; } ph;
    ph.h[0] = __float2half_rn(v.x);
    ph.h[1] = __float2half_rn(v.y);
    ph.h[2] = __float2half_rn(v.z);
    ph.h[3] = __float2half_rn(v.w);
    ((uint2*)dh)[off] = ph.u;
}

// ---------------------------------------------------------------------------
// QKV GEMM (fp16, fp32 accum). BM=128, BN=96, BK=64, 2-stage cp.async.
// Q pre-scaled by 1/sqrt(96). grid=(64, 8, 3).
// ---------------------------------------------------------------------------
#define QK_LDA 72
#define QK_LDB 104

__device__ __forceinline__ void qkv_load(
    __half* Ah, __half* Bh,
    const __half* gXh, const __half* gWh,
    int p, int m0, int kt, size_t wbase, int tid)
{
    #pragma unroll
    for (int j = 0; j < 7; j++) {
        int c = tid + j * 256;             // 0..1791
        if (c < 1024) {
            int row = c >> 3, off = (c & 7) * 8;
            CPA(su32(Ah + p * (128*QK_LDA) + row * QK_LDA + off),
                gXh + (size_t)(m0 + row) * DD + kt + off);
        } else {
            int c2 = c - 1024;             // 0..767
            int row = c2 / 12, off = (c2 - row * 12) * 8;
            CPA(su32(Bh + p * (64*QK_LDB) + row * QK_LDB + off),
                gWh + wbase + (size_t)(kt + row) * DHH + off);
        }
    }
}

__global__ __launch_bounds__(256, 2) void qkv_kernel(
    const float* __restrict__ bq, const float* __restrict__ bk, const float* __restrict__ bv)
{
    extern __shared__ __half smq[];
    __half* Ah = smq;                      // 2 x 128 x 72
    __half* Bh = Ah + 2*128*QK_LDA;        // 2 x 64 x 104

    const __half *gXh, *gWh; const float* bias; __half *oh;
    if (blockIdx.z == 0)      { gXh=g_Xqh; gWh=g_Wqh; bias=bq; oh=g_Qh; }
    else if (blockIdx.z == 1) { gXh=g_Xkh; gWh=g_Wkh; bias=bk; oh=g_Kh; }
    else                      { gXh=g_Xvh; gWh=g_Wvh; bias=bv; oh=g_Vh; }
    const float oscale = (blockIdx.z == 0) ? rsqrtf(96.0f) : 1.0f;

    const int h   = blockIdx.y;
    const int m0  = blockIdx.x * 128;
    const int tid = threadIdx.x;
    const int wid = tid >> 5, lane = tid & 31;
    const int wm  = wid >> 1, wn = wid & 1;
    const size_t wbase = (size_t)h * DD * DHH;

    float acc[2][6][4];
    #pragma unroll
    for (int i = 0; i < 2; i++)
        #pragma unroll
        for (int j = 0; j < 6; j++)
            #pragma unroll
            for (int k = 0; k < 4; k++) acc[i][j][k] = 0.f;

    const int lrow = lane & 15, lcol8 = (lane >> 4) << 3;

    qkv_load(Ah, Bh, gXh, gWh, 0, m0, 0, wbase, tid);
    CP_COMMIT;

    const int NT = DD / 64;   // 12
    for (int it = 0; it < NT; it++) {
        int p = it & 1;
        if (it + 1 < NT) {
            qkv_load(Ah, Bh, gXh, gWh, (it+1)&1, m0, (it+1)*64, wbase, tid);
            CP_COMMIT;
            CP_WAIT1;
        } else {
            CP_WAIT0;
        }
        __syncthreads();

        __half* Ahp = Ah + p * (128*QK_LDA);
        __half* Bhp = Bh + p * (64*QK_LDB);

        #pragma unroll
        for (int ks = 0; ks < 4; ks++) {
            int k0 = ks * 16;
            unsigned ah[2][4];
            #pragma unroll
            for (int mf = 0; mf < 2; mf++) {
                int row = wm * 32 + mf * 16 + lrow;
                ldsm4(ah[mf], su32(Ahp + row * QK_LDA + k0 + lcol8));
            }
            #pragma unroll
            for (int nf2 = 0; nf2 < 3; nf2++) {
                unsigned bh[4];
                int n0 = wn * 48 + nf2 * 16;
                ldsm4t(bh, su32(Bhp + (k0 + lrow) * QK_LDB + n0 + lcol8));
                #pragma unroll
                for (int hn = 0; hn < 2; hn++) {
                    #pragma unroll
                    for (int mf = 0; mf < 2; mf++)
                        mma16816(acc[mf][nf2*2 + hn], ah[mf], bh + hn*2);
                }
            }
        }
        __syncthreads();
    }

    #pragma unroll
    for (int mf = 0; mf < 2; mf++) {
        #pragma unroll
        for (int nf = 0; nf < 6; nf++) {
            int col = wn * 48 + nf * 8 + (lane & 3) * 2;
            float b0 = bias[h*DHH + col], b1 = bias[h*DHH + col + 1];
            #pragma unroll
            for (int hr = 0; hr < 2; hr++) {
                int m = m0 + wm * 32 + mf * 16 + (lane >> 2) + hr * 8;
                int bb = m >> 11, s = m & 2047;
                size_t off = (((size_t)(bb * HH + h)) * SS + s) * DHH + col;
                float v0 = (acc[mf][nf][hr*2 + 0] + b0) * oscale;
                float v1 = (acc[mf][nf][hr*2 + 1] + b1) * oscale;
                *(half2*)(oh + off) = __halves2half2(__float2half_rn(v0), __float2half_rn(v1));
            }
        }
    }
}

// ---------------------------------------------------------------------------
// Flash attention, fp16 mma, 3-stage KV pipeline. Q region reused as stage 3.
// ---------------------------------------------------------------------------
#define AT_LD 104
#define KV_REG (2*64*AT_LD)

__device__ __forceinline__ void attn_load_kv(__half* Kbuf, size_t gbase, int tid)
{
    __half* Vbuf = Kbuf + 64 * AT_LD;
    #pragma unroll
    for (int j = 0; j < 6; j++) {
        int c = tid + j * 256;
        int arr = (c >= 768) ? 1 : 0;
        int rem = c - arr * 768;
        int row = rem / 12;
        int off = (rem - row * 12) * 8;
        const __half* sp = (arr ? g_Vh : g_Kh) + (gbase + row) * DHH + off;
        __half* dp = (arr ? Vbuf : Kbuf) + row * AT_LD + off;
        CPA(su32(dp), sp);
    }
}

__global__ __launch_bounds__(256, 2) void attn_kernel()
{
    extern __shared__ __half smh[];
    __half* R0 = smh;
    __half* R1 = smh + KV_REG;
    __half* R2 = smh + 2 * KV_REG;

    const int b  = blockIdx.z, h = blockIdx.y;
    const int s0 = blockIdx.x * 128;
    const int tid = threadIdx.x, wid = tid >> 5, lane = tid & 31;
    const size_t base = ((size_t)(b * HH + h)) * SS;

    {   // load Q tile into region 0
        int r = tid >> 1, c0 = (tid & 1) * 48;
        size_t go = (base + s0 + r) * DHH + c0;
        __half* dh = R0 + r * AT_LD + c0;
        #pragma unroll
        for (int i = 0; i < 6; i++)
            *(uint4*)(dh + i*8) = *(const uint4*)(g_Qh + go + i*8);
    }

    attn_load_kv(R1, base, tid);      CP_COMMIT;
    attn_load_kv(R2, base + 64, tid); CP_COMMIT;

    const int lrow = lane & 15, lcol8 = (lane >> 4) << 3;
    const int krow_off = (lane & 7) + ((lane & 16) >> 1);
    const int kcol_off = (lane & 8);

    __syncthreads();
    unsigned qf[6][4];
    {
        int qrow = wid * 16 + lrow;
        #pragma unroll
        for (int dk = 0; dk < 6; dk++)
            ldsm4(qf[dk], su32(R0 + qrow * AT_LD + dk * 16 + lcol8));
    }
    __syncthreads();

    attn_load_kv(R0, base + 128, tid); CP_COMMIT;

    float oacc[12][4];
    #pragma unroll
    for (int j = 0; j < 12; j++)
        #pragma unroll
        for (int t = 0; t < 4; t++) oacc[j][t] = 0.f;
    float m0r = -1e30f, m1r = -1e30f, l0r = 0.f, l1r = 0.f;

    const int NT = SS / 64;
    int cur = 1;
    for (int it = 0; it < NT; it++) {
        if (it < NT - 2)      { CP_WAIT2; }
        else if (it == NT - 2){ CP_WAIT1; }
        else                  { CP_WAIT0; }
        __syncthreads();

        __half* Kp = smh + cur * KV_REG;
        __half* Vp = Kp + 64 * AT_LD;

        float sacc[8][4];
        #pragma unroll
        for (int j = 0; j < 8; j++)
            #pragma unroll
            for (int t = 0; t < 4; t++) sacc[j][t] = 0.f;

        #pragma unroll
        for (int dk = 0; dk < 6; dk++) {
            int d0 = dk * 16;
            #pragma unroll
            for (int nf2 = 0; nf2 < 4; nf2++) {
                unsigned bh[4];
                ldsm4(bh, su32(Kp + (nf2 * 16 + krow_off) * AT_LD + d0 + kcol_off));
                mma16816(sacc[nf2*2 + 0], qf[dk], bh + 0);
                mma16816(sacc[nf2*2 + 1], qf[dk], bh + 2);
            }
        }

        float mx0 = -1e30f, mx1 = -1e30f;
        #pragma unroll
        for (int j = 0; j < 8; j++) {
            mx0 = fmaxf(mx0, fmaxf(sacc[j][0], sacc[j][1]));
            mx1 = fmaxf(mx1, fmaxf(sacc[j][2], sacc[j][3]));
        }
        mx0 = fmaxf(mx0, __shfl_xor_sync(0xffffffffu, mx0, 1));
        mx0 = fmaxf(mx0, __shfl_xor_sync(0xffffffffu, mx0, 2));
        mx1 = fmaxf(mx1, __shfl_xor_sync(0xffffffffu, mx1, 1));
        mx1 = fmaxf(mx1, __shfl_xor_sync(0xffffffffu, mx1, 2));
        float mn0 = fmaxf(m0r, mx0), mn1 = fmaxf(m1r, mx1);
        float corr0 = __expf(m0r - mn0), corr1 = __expf(m1r - mn1);
        m0r = mn0; m1r = mn1;
        float sum0 = 0.f, sum1 = 0.f;
        #pragma unroll
        for (int j = 0; j < 8; j++) {
            sacc[j][0] = __expf(sacc[j][0] - mn0);
            sacc[j][1] = __expf(sacc[j][1] - mn0);
            sacc[j][2] = __expf(sacc[j][2] - mn1);
            sacc[j][3] = __expf(sacc[j][3] - mn1);
            sum0 += sacc[j][0] + sacc[j][1];
            sum1 += sacc[j][2] + sacc[j][3];
        }
        sum0 += __shfl_xor_sync(0xffffffffu, sum0, 1);
        sum0 += __shfl_xor_sync(0xffffffffu, sum0, 2);
        sum1 += __shfl_xor_sync(0xffffffffu, sum1, 1);
        sum1 += __shfl_xor_sync(0xffffffffu, sum1, 2);
        l0r = l0r * corr0 + sum0;
        l1r = l1r * corr1 + sum1;

        #pragma unroll
        for (int j = 0; j < 12; j++) {
            oacc[j][0] *= corr0; oacc[j][1] *= corr0;
            oacc[j][2] *= corr1; oacc[j][3] *= corr1;
        }

        unsigned ph[4][4];
        #pragma unroll
        for (int kf = 0; kf < 4; kf++) {
            #pragma unroll
            for (int q = 0; q < 4; q++) {
                int fj = kf*2 + (q >> 1);
                int t0 = (q & 1) * 2;
                ph[kf][q] = h2u(__halves2half2(__float2half_rn(sacc[fj][t0]),
                                               __float2half_rn(sacc[fj][t0 + 1])));
            }
        }

        #pragma unroll
        for (int kf = 0; kf < 4; kf++) {
            int k0 = kf * 16;
            #pragma unroll
            for (int nf2 = 0; nf2 < 6; nf2++) {
                unsigned bh[4];
                ldsm4t(bh, su32(Vp + (k0 + lrow) * AT_LD + nf2 * 16 + lcol8));
                mma16816(oacc[nf2*2 + 0], ph[kf], bh + 0);
                mma16816(oacc[nf2*2 + 1], ph[kf], bh + 2);
            }
        }
        __syncthreads();
        if (it + 3 < NT) {
            attn_load_kv(Kp, base + (size_t)(it + 3) * 64, tid);
            CP_COMMIT;
        }
        cur = (cur == 2) ? 0 : cur + 1;
    }

    float inv0 = 1.0f / l0r, inv1 = 1.0f / l1r;
    #pragma unroll
    for (int nf = 0; nf < 12; nf++) {
        int col = h * DHH + nf * 8 + (lane & 3) * 2;
        #pragma unroll
        for (int hr = 0; hr < 2; hr++) {
            int s = s0 + wid * 16 + (lane >> 2) + hr * 8;
            size_t off = ((size_t)b * SS + s) * DD + col;
            float inv = hr ? inv1 : inv0;
            float v0 = oacc[nf][hr*2 + 0] * inv;
            float v1 = oacc[nf][hr*2 + 1] * inv;
            *(half2*)(g_cath + off) = __halves2half2(__float2half_rn(v0), __float2half_rn(v1));
        }
    }
}

// ---------------------------------------------------------------------------
// Output projection (fp16): out = cath @ Woh + bo. BM=128, BN=128, BK=64.
// ---------------------------------------------------------------------------
#define OP_LDA 72
#define OP_LDB 136

__device__ __forceinline__ void oproj_load(
    __half* Ah, __half* Bh, int p, int m0, int n0b, int kt, int tid)
{
    #pragma unroll
    for (int j = 0; j < 8; j++) {
        int c = tid + j * 256;
        if (c < 1024) {
            int row = c >> 3, off = (c & 7) * 8;
            CPA(su32(Ah + p * (128*OP_LDA) + row * OP_LDA + off),
                g_cath + (size_t)(m0 + row) * DD + kt + off);
        } else {
            int c2 = c - 1024;
            int row = c2 >> 4, off = (c2 & 15) * 8;
            CPA(su32(Bh + p * (64*OP_LDB) + row * OP_LDB + off),
                g_Woh + (size_t)(kt + row) * DD + n0b + off);
        }
    }
}

__global__ __launch_bounds__(256, 2) void oproj_kernel(
    const float* __restrict__ bo, float* __restrict__ out)
{
    extern __shared__ __half smo[];
    __half* Ah = smo;
    __half* Bh = Ah + 2*128*OP_LDA;

    const int m0  = blockIdx.x * 128;
    const int n0b = blockIdx.y * 128;
    const int tid = threadIdx.x, wid = tid >> 5, lane = tid & 31;
    const int wm = wid >> 1, wn = wid & 1;

    float acc[2][8][4];
    #pragma unroll
    for (int i = 0; i < 2; i++)
        #pragma unroll
        for (int j = 0; j < 8; j++)
            #pragma unroll
            for (int k = 0; k < 4; k++) acc[i][j][k] = 0.f;

    const int lrow = lane & 15, lcol8 = (lane >> 4) << 3;

    oproj_load(Ah, Bh, 0, m0, n0b, 0, tid);
    CP_COMMIT;

    const int NT = DD / 64;
    for (int it = 0; it < NT; it++) {
        int p = it & 1;
        if (it + 1 < NT) {
            oproj_load(Ah, Bh, (it+1)&1, m0, n0b, (it+1)*64, tid);
            CP_COMMIT;
            CP_WAIT1;
        } else {
            CP_WAIT0;
        }
        __syncthreads();

        __half* Ahp = Ah + p * (128*OP_LDA);
        __half* Bhp = Bh + p * (64*OP_LDB);

        #pragma unroll
        for (int ks = 0; ks < 4; ks++) {
            int k0 = ks * 16;
            unsigned ah[2][4];
            #pragma unroll
            for (int mf = 0; mf < 2; mf++) {
                int row = wm * 32 + mf * 16 + lrow;
                ldsm4(ah[mf], su32(Ahp + row * OP_LDA + k0 + lcol8));
            }
            #pragma unroll
            for (int nf2 = 0; nf2 < 4; nf2++) {
                unsigned bh[4];
                int n0 = wn * 64 + nf2 * 16;
                ldsm4t(bh, su32(Bhp + (k0 + lrow) * OP_LDB + n0 + lcol8));
                #pragma unroll
                for (int hn = 0; hn < 2; hn++) {
                    #pragma unroll
                    for (int mf = 0; mf < 2; mf++)
                        mma16816(acc[mf][nf2*2 + hn], ah[mf], bh + hn*2);
                }
            }
        }
        __syncthreads();
    }

    #pragma unroll
    for (int mf = 0; mf < 2; mf++) {
        #pragma unroll
        for (int nf = 0; nf < 8; nf++) {
            int col = n0b + wn * 64 + nf * 8 + (lane & 3) * 2;
            float b0 = bo[col], b1 = bo[col + 1];
            #pragma unroll
            for (int hr = 0; hr < 2; hr++) {
                int m = m0 + wm * 32 + mf * 16 + (lane >> 2) + hr * 8;
                float2 v = make_float2(acc[mf][nf][hr*2+0] + b0,
                                       acc[mf][nf][hr*2+1] + b1);
                *(float2*)(out + (size_t)m * DD + col) = v;
            }
        }
    }
}

// ---------------------------------------------------------------------------
extern "C" void kernel_launch(void* const* d_in, const int* in_sizes, int n_in,
                              void* d_out, int out_size)
{
    (void)in_sizes; (void)n_in; (void)out_size;
    const float* Xq = (const float*)d_in[0];
    const float* Xk = (const float*)d_in[1];
    const float* Xv = (const float*)d_in[2];
    const float* Wq = (const float*)d_in[3];
    const float* bq = (const float*)d_in[4];
    const float* Wk = (const float*)d_in[5];
    const float* bk = (const float*)d_in[6];
    const float* Wv = (const float*)d_in[7];
    const float* bv = (const float*)d_in[8];
    const float* Wo = (const float*)d_in[9];
    const float* bo = (const float*)d_in[10];
    float* out = (float*)d_out;

    const int total4 = 3*NX4 + 4*NW4;
    convert_all<<<(total4 + 255) / 256, 256>>>(Xq, Xk, Xv, Wq, Wk, Wv, Wo);

    const int smem_qkv = (2*128*QK_LDA + 2*64*QK_LDB) * (int)sizeof(__half);   // 63488
    cudaFuncSetAttribute(qkv_kernel, cudaFuncAttributeMaxDynamicSharedMemorySize, smem_qkv);
    dim3 gq(MM / 128, HH, 3);
    qkv_kernel<<<gq, 256, smem_qkv>>>(bq, bk, bv);

    const int smem_attn = 3 * KV_REG * (int)sizeof(__half);                    // 79872
    cudaFuncSetAttribute(attn_kernel, cudaFuncAttributeMaxDynamicSharedMemorySize, smem_attn);
    dim3 ga(SS / 128, HH, BB);
    attn_kernel<<<ga, 256, smem_attn>>>();

    const int smem_op = (2*128*OP_LDA + 2*64*OP_LDB) * (int)sizeof(__half);    // 71680
    cudaFuncSetAttribute(oproj_kernel, cudaFuncAttributeMaxDynamicSharedMemorySize, smem_op);
    dim3 go(MM / 128, DD / 128);
    oproj_kernel<<<go, 256, smem_op>>>(bo, out);
}

// round 15
// speedup vs baseline: 1.5198x; 1.0140x over previous
#include <cuda_runtime.h>
#include <cuda_fp16.h>

#define BB 4
#define SS 2048
#define DD 768
#define HH 8
#define DHH 96
#define MM (BB*SS)   // 8192

// Pure fp16 scratch (fp32 accumulate in mma)
__device__ __half g_Xqh[(size_t)MM*DD];
__device__ __half g_Xkh[(size_t)MM*DD];
__device__ __half g_Xvh[(size_t)MM*DD];
__device__ __half g_Wqh[(size_t)HH*DD*DHH];
__device__ __half g_Wkh[(size_t)HH*DD*DHH];
__device__ __half g_Wvh[(size_t)HH*DD*DHH];
__device__ __half g_Woh[(size_t)DD*DD];
__device__ __half g_Qh[(size_t)BB*HH*SS*DHH];   // pre-scaled by log2e/sqrt(96)
__device__ __half g_Kh[(size_t)BB*HH*SS*DHH];
__device__ __half g_Vh[(size_t)BB*HH*SS*DHH];
__device__ __half g_cath[(size_t)MM*DD];

__device__ __forceinline__ unsigned su32(const void* p) {
    return (unsigned)__cvta_generic_to_shared(p);
}
// packed fp32x2 -> fp16x2 (lo in low half)
__device__ __forceinline__ unsigned cvt2h(float lo, float hi) {
    unsigned r;
    asm("cvt.rn.f16x2.f32 %0, %1, %2;" : "=r"(r) : "f"(hi), "f"(lo));
    return r;
}
__device__ __forceinline__ void ldsm4(unsigned r[4], unsigned addr) {
    asm volatile("ldmatrix.sync.aligned.m8n8.x4.shared.b16 {%0,%1,%2,%3},[%4];\n"
        : "=r"(r[0]), "=r"(r[1]), "=r"(r[2]), "=r"(r[3]) : "r"(addr));
}
__device__ __forceinline__ void ldsm4t(unsigned r[4], unsigned addr) {
    asm volatile("ldmatrix.sync.aligned.m8n8.x4.trans.shared.b16 {%0,%1,%2,%3},[%4];\n"
        : "=r"(r[0]), "=r"(r[1]), "=r"(r[2]), "=r"(r[3]) : "r"(addr));
}
__device__ __forceinline__ void mma16816(float* c, const unsigned* a, const unsigned* b) {
    asm volatile("mma.sync.aligned.m16n8k16.row.col.f32.f16.f16.f32 "
        "{%0,%1,%2,%3},{%4,%5,%6,%7},{%8,%9},{%0,%1,%2,%3};\n"
        : "+f"(c[0]), "+f"(c[1]), "+f"(c[2]), "+f"(c[3])
        : "r"(a[0]), "r"(a[1]), "r"(a[2]), "r"(a[3]), "r"(b[0]), "r"(b[1]));
}
#define CPA(dst, src) asm volatile("cp.async.cg.shared.global [%0], [%1], 16;\n" :: "r"(dst), "l"(src))
#define CP_COMMIT asm volatile("cp.async.commit_group;\n")
#define CP_WAIT2  asm volatile("cp.async.wait_group 2;\n")
#define CP_WAIT1  asm volatile("cp.async.wait_group 1;\n")
#define CP_WAIT0  asm volatile("cp.async.wait_group 0;\n")

// ---------------------------------------------------------------------------
// Preconvert fp32 -> fp16 (all 7 tensors, one launch)
// ---------------------------------------------------------------------------
#define NX4 (MM*DD/4)          // 1572864
#define NW4 (HH*DD*DHH/4)      // 147456

__global__ __launch_bounds__(256) void convert_all(
    const float* __restrict__ Xq, const float* __restrict__ Xk, const float* __restrict__ Xv,
    const float* __restrict__ Wq, const float* __restrict__ Wk, const float* __restrict__ Wv,
    const float* __restrict__ Wo)
{
    int i = blockIdx.x * 256 + threadIdx.x;
    const float* src; __half* dh; int off;
    if (i < 3 * NX4) {
        int t = i / NX4; off = i - t * NX4;
        src = (t == 0) ? Xq : (t == 1) ? Xk : Xv;
        dh  = (t == 0) ? g_Xqh : (t == 1) ? g_Xkh : g_Xvh;
    } else {
        int j = i - 3 * NX4;
        if (j >= 4 * NW4) return;
        int t = j / NW4; off = j - t * NW4;
        src = (t == 0) ? Wq : (t == 1) ? Wk : (t == 2) ? Wv : Wo;
        dh  = (t == 0) ? g_Wqh : (t == 1) ? g_Wkh : (t == 2) ? g_Wvh : g_Woh;
    }
    float4 v = ((const float4*)src)[off];
    uint2 u;
    u.x = cvt2h(v.x, v.y);
    u.y = cvt2h(v.z, v.w);
    ((uint2*)dh)[off] = u;
}

// ---------------------------------------------------------------------------
// QKV GEMM (fp16, fp32 accum). BM=128, BN=96, BK=64, 2-stage cp.async.
// Q pre-scaled by log2e/sqrt(96) (softmax in base-2). grid=(64, 8, 3).
// ---------------------------------------------------------------------------
#define QK_LDA 72
#define QK_LDB 104

__device__ __forceinline__ void qkv_load(
    __half* Ah, __half* Bh,
    const __half* gXh, const __half* gWh,
    int p, int m0, int kt, size_t wbase, int tid)
{
    #pragma unroll
    for (int j = 0; j < 7; j++) {
        int c = tid + j * 256;             // 0..1791
        if (c < 1024) {
            int row = c >> 3, off = (c & 7) * 8;
            CPA(su32(Ah + p * (128*QK_LDA) + row * QK_LDA + off),
                gXh + (size_t)(m0 + row) * DD + kt + off);
        } else {
            int c2 = c - 1024;             // 0..767
            int row = c2 / 12, off = (c2 - row * 12) * 8;
            CPA(su32(Bh + p * (64*QK_LDB) + row * QK_LDB + off),
                gWh + wbase + (size_t)(kt + row) * DHH + off);
        }
    }
}

__global__ __launch_bounds__(256, 2) void qkv_kernel(
    const float* __restrict__ bq, const float* __restrict__ bk, const float* __restrict__ bv)
{
    extern __shared__ __half smq[];
    __half* Ah = smq;                      // 2 x 128 x 72
    __half* Bh = Ah + 2*128*QK_LDA;        // 2 x 64 x 104

    const __half *gXh, *gWh; const float* bias; __half *oh;
    if (blockIdx.z == 0)      { gXh=g_Xqh; gWh=g_Wqh; bias=bq; oh=g_Qh; }
    else if (blockIdx.z == 1) { gXh=g_Xkh; gWh=g_Wkh; bias=bk; oh=g_Kh; }
    else                      { gXh=g_Xvh; gWh=g_Wvh; bias=bv; oh=g_Vh; }
    // Q carries softmax scale AND log2(e) so attention uses exp2
    const float oscale = (blockIdx.z == 0) ? rsqrtf(96.0f) * 1.4426950408889634f : 1.0f;

    const int h   = blockIdx.y;
    const int m0  = blockIdx.x * 128;
    const int tid = threadIdx.x;
    const int wid = tid >> 5, lane = tid & 31;
    const int wm  = wid >> 1, wn = wid & 1;
    const size_t wbase = (size_t)h * DD * DHH;

    float acc[2][6][4];
    #pragma unroll
    for (int i = 0; i < 2; i++)
        #pragma unroll
        for (int j = 0; j < 6; j++)
            #pragma unroll
            for (int k = 0; k < 4; k++) acc[i][j][k] = 0.f;

    const int lrow = lane & 15, lcol8 = (lane >> 4) << 3;

    qkv_load(Ah, Bh, gXh, gWh, 0, m0, 0, wbase, tid);
    CP_COMMIT;

    const int NT = DD / 64;   // 12
    for (int it = 0; it < NT; it++) {
        int p = it & 1;
        if (it + 1 < NT) {
            qkv_load(Ah, Bh, gXh, gWh, (it+1)&1, m0, (it+1)*64, wbase, tid);
            CP_COMMIT;
            CP_WAIT1;
        } else {
            CP_WAIT0;
        }
        __syncthreads();

        __half* Ahp = Ah + p * (128*QK_LDA);
        __half* Bhp = Bh + p * (64*QK_LDB);

        #pragma unroll
        for (int ks = 0; ks < 4; ks++) {
            int k0 = ks * 16;
            unsigned ah[2][4];
            #pragma unroll
            for (int mf = 0; mf < 2; mf++) {
                int row = wm * 32 + mf * 16 + lrow;
                ldsm4(ah[mf], su32(Ahp + row * QK_LDA + k0 + lcol8));
            }
            #pragma unroll
            for (int nf2 = 0; nf2 < 3; nf2++) {
                unsigned bh[4];
                int n0 = wn * 48 + nf2 * 16;
                ldsm4t(bh, su32(Bhp + (k0 + lrow) * QK_LDB + n0 + lcol8));
                #pragma unroll
                for (int hn = 0; hn < 2; hn++) {
                    #pragma unroll
                    for (int mf = 0; mf < 2; mf++)
                        mma16816(acc[mf][nf2*2 + hn], ah[mf], bh + hn*2);
                }
            }
        }
        __syncthreads();
    }

    #pragma unroll
    for (int mf = 0; mf < 2; mf++) {
        #pragma unroll
        for (int nf = 0; nf < 6; nf++) {
            int col = wn * 48 + nf * 8 + (lane & 3) * 2;
            float b0 = bias[h*DHH + col], b1 = bias[h*DHH + col + 1];
            #pragma unroll
            for (int hr = 0; hr < 2; hr++) {
                int m = m0 + wm * 32 + mf * 16 + (lane >> 2) + hr * 8;
                int bb = m >> 11, s = m & 2047;
                size_t off = (((size_t)(bb * HH + h)) * SS + s) * DHH + col;
                float v0 = (acc[mf][nf][hr*2 + 0] + b0) * oscale;
                float v1 = (acc[mf][nf][hr*2 + 1] + b1) * oscale;
                *(unsigned*)(oh + off) = cvt2h(v0, v1);
            }
        }
    }
}

// ---------------------------------------------------------------------------
// Flash attention, fp16 mma, 3-region KV pipeline, base-2 softmax.
// Single wave: grid=(8,8,4)=256 blocks; each block does 2 sequential
// 128-row Q-chunks (oacc/m/l reset per chunk, pipeline restarts).
// ---------------------------------------------------------------------------
#define AT_LD 104
#define KV_REG (2*64*AT_LD)

__device__ __forceinline__ void attn_load_kv(__half* Kbuf, size_t gbase, int tid)
{
    __half* Vbuf = Kbuf + 64 * AT_LD;
    #pragma unroll
    for (int j = 0; j < 6; j++) {
        int c = tid + j * 256;
        int arr = (c >= 768) ? 1 : 0;
        int rem = c - arr * 768;
        int row = rem / 12;
        int off = (rem - row * 12) * 8;
        const __half* sp = (arr ? g_Vh : g_Kh) + (gbase + row) * DHH + off;
        __half* dp = (arr ? Vbuf : Kbuf) + row * AT_LD + off;
        CPA(su32(dp), sp);
    }
}

__global__ __launch_bounds__(256, 2) void attn_kernel()
{
    extern __shared__ __half smh[];
    __half* R0 = smh;
    __half* R1 = smh + KV_REG;
    __half* R2 = smh + 2 * KV_REG;

    const int b  = blockIdx.z, h = blockIdx.y;
    const int tid = threadIdx.x, wid = tid >> 5, lane = tid & 31;
    const size_t base = ((size_t)(b * HH + h)) * SS;

    const int lrow = lane & 15, lcol8 = (lane >> 4) << 3;
    const int krow_off = (lane & 7) + ((lane & 16) >> 1);
    const int kcol_off = (lane & 8);
    const int NT = SS / 64;   // 32

    for (int qc = 0; qc < 2; qc++) {
        const int s0 = blockIdx.x * 256 + qc * 128;

        {   // load Q chunk into region 0 (all prior work drained)
            int r = tid >> 1, c0 = (tid & 1) * 48;
            size_t go = (base + s0 + r) * DHH + c0;
            __half* dh = R0 + r * AT_LD + c0;
            #pragma unroll
            for (int i = 0; i < 6; i++)
                *(uint4*)(dh + i*8) = *(const uint4*)(g_Qh + go + i*8);
        }

        attn_load_kv(R1, base, tid);      CP_COMMIT;   // tile 0
        attn_load_kv(R2, base + 64, tid); CP_COMMIT;   // tile 1

        __syncthreads();   // Q ready
        unsigned qf[6][4];
        {
            int qrow = wid * 16 + lrow;
            #pragma unroll
            for (int dk = 0; dk < 6; dk++)
                ldsm4(qf[dk], su32(R0 + qrow * AT_LD + dk * 16 + lcol8));
        }
        __syncthreads();   // region 0 reusable

        attn_load_kv(R0, base + 128, tid); CP_COMMIT;  // tile 2

        float oacc[12][4];
        #pragma unroll
        for (int j = 0; j < 12; j++)
            #pragma unroll
            for (int t = 0; t < 4; t++) oacc[j][t] = 0.f;
        float m0r = -1e30f, m1r = -1e30f, l0r = 0.f, l1r = 0.f;

        int cur = 1;
        for (int it = 0; it < NT; it++) {
            if (it < NT - 2)      { CP_WAIT2; }
            else if (it == NT - 2){ CP_WAIT1; }
            else                  { CP_WAIT0; }
            __syncthreads();

            __half* Kp = smh + cur * KV_REG;
            __half* Vp = Kp + 64 * AT_LD;

            // S = Q @ K^T (log2 domain)
            float sacc[8][4];
            #pragma unroll
            for (int j = 0; j < 8; j++)
                #pragma unroll
                for (int t = 0; t < 4; t++) sacc[j][t] = 0.f;

            #pragma unroll
            for (int dk = 0; dk < 6; dk++) {
                int d0 = dk * 16;
                #pragma unroll
                for (int nf2 = 0; nf2 < 4; nf2++) {
                    unsigned bh[4];
                    ldsm4(bh, su32(Kp + (nf2 * 16 + krow_off) * AT_LD + d0 + kcol_off));
                    mma16816(sacc[nf2*2 + 0], qf[dk], bh + 0);
                    mma16816(sacc[nf2*2 + 1], qf[dk], bh + 2);
                }
            }

            // online softmax (base-2)
            float mx0 = -1e30f, mx1 = -1e30f;
            #pragma unroll
            for (int j = 0; j < 8; j++) {
                mx0 = fmaxf(mx0, fmaxf(sacc[j][0], sacc[j][1]));
                mx1 = fmaxf(mx1, fmaxf(sacc[j][2], sacc[j][3]));
            }
            mx0 = fmaxf(mx0, __shfl_xor_sync(0xffffffffu, mx0, 1));
            mx0 = fmaxf(mx0, __shfl_xor_sync(0xffffffffu, mx0, 2));
            mx1 = fmaxf(mx1, __shfl_xor_sync(0xffffffffu, mx1, 1));
            mx1 = fmaxf(mx1, __shfl_xor_sync(0xffffffffu, mx1, 2));
            float mn0 = fmaxf(m0r, mx0), mn1 = fmaxf(m1r, mx1);
            float corr0 = exp2f(m0r - mn0), corr1 = exp2f(m1r - mn1);
            m0r = mn0; m1r = mn1;
            float sum0 = 0.f, sum1 = 0.f;
            #pragma unroll
            for (int j = 0; j < 8; j++) {
                sacc[j][0] = exp2f(sacc[j][0] - mn0);
                sacc[j][1] = exp2f(sacc[j][1] - mn0);
                sacc[j][2] = exp2f(sacc[j][2] - mn1);
                sacc[j][3] = exp2f(sacc[j][3] - mn1);
                sum0 += sacc[j][0] + sacc[j][1];
                sum1 += sacc[j][2] + sacc[j][3];
            }
            sum0 += __shfl_xor_sync(0xffffffffu, sum0, 1);
            sum0 += __shfl_xor_sync(0xffffffffu, sum0, 2);
            sum1 += __shfl_xor_sync(0xffffffffu, sum1, 1);
            sum1 += __shfl_xor_sync(0xffffffffu, sum1, 2);
            l0r = l0r * corr0 + sum0;
            l1r = l1r * corr1 + sum1;

            #pragma unroll
            for (int j = 0; j < 12; j++) {
                oacc[j][0] *= corr0; oacc[j][1] *= corr0;
                oacc[j][2] *= corr1; oacc[j][3] *= corr1;
            }

            // P fragments (packed cvt)
            unsigned ph[4][4];
            #pragma unroll
            for (int kf = 0; kf < 4; kf++) {
                #pragma unroll
                for (int q = 0; q < 4; q++) {
                    int fj = kf*2 + (q >> 1);
                    int t0 = (q & 1) * 2;
                    ph[kf][q] = cvt2h(sacc[fj][t0], sacc[fj][t0 + 1]);
                }
            }

            // O += P @ V
            #pragma unroll
            for (int kf = 0; kf < 4; kf++) {
                int k0 = kf * 16;
                #pragma unroll
                for (int nf2 = 0; nf2 < 6; nf2++) {
                    unsigned bh[4];
                    ldsm4t(bh, su32(Vp + (k0 + lrow) * AT_LD + nf2 * 16 + lcol8));
                    mma16816(oacc[nf2*2 + 0], ph[kf], bh + 0);
                    mma16816(oacc[nf2*2 + 1], ph[kf], bh + 2);
                }
            }
            __syncthreads();
            if (it + 3 < NT) {
                attn_load_kv(Kp, base + (size_t)(it + 3) * 64, tid);
                CP_COMMIT;
            }
            cur = (cur == 2) ? 0 : cur + 1;
        }

        // Epilogue: normalize, store cat (fp16, packed cvt)
        float inv0 = 1.0f / l0r, inv1 = 1.0f / l1r;
        #pragma unroll
        for (int nf = 0; nf < 12; nf++) {
            int col = h * DHH + nf * 8 + (lane & 3) * 2;
            #pragma unroll
            for (int hr = 0; hr < 2; hr++) {
                int s = s0 + wid * 16 + (lane >> 2) + hr * 8;
                size_t off = ((size_t)b * SS + s) * DD + col;
                float inv = hr ? inv1 : inv0;
                *(unsigned*)(g_cath + off) =
                    cvt2h(oacc[nf][hr*2 + 0] * inv, oacc[nf][hr*2 + 1] * inv);
            }
        }
        __syncthreads();   // all warps done before next chunk reuses regions
    }
}

// ---------------------------------------------------------------------------
// Output projection (fp16): out = cath @ Woh + bo. BM=128, BN=128, BK=64.
// ---------------------------------------------------------------------------
#define OP_LDA 72
#define OP_LDB 136

__device__ __forceinline__ void oproj_load(
    __half* Ah, __half* Bh, int p, int m0, int n0b, int kt, int tid)
{
    #pragma unroll
    for (int j = 0; j < 8; j++) {
        int c = tid + j * 256;
        if (c < 1024) {
            int row = c >> 3, off = (c & 7) * 8;
            CPA(su32(Ah + p * (128*OP_LDA) + row * OP_LDA + off),
                g_cath + (size_t)(m0 + row) * DD + kt + off);
        } else {
            int c2 = c - 1024;
            int row = c2 >> 4, off = (c2 & 15) * 8;
            CPA(su32(Bh + p * (64*OP_LDB) + row * OP_LDB + off),
                g_Woh + (size_t)(kt + row) * DD + n0b + off);
        }
    }
}

__global__ __launch_bounds__(256, 2) void oproj_kernel(
    const float* __restrict__ bo, float* __restrict__ out)
{
    extern __shared__ __half smo[];
    __half* Ah = smo;
    __half* Bh = Ah + 2*128*OP_LDA;

    const int m0  = blockIdx.x * 128;
    const int n0b = blockIdx.y * 128;
    const int tid = threadIdx.x, wid = tid >> 5, lane = tid & 31;
    const int wm = wid >> 1, wn = wid & 1;

    float acc[2][8][4];
    #pragma unroll
    for (int i = 0; i < 2; i++)
        #pragma unroll
        for (int j = 0; j < 8; j++)
            #pragma unroll
            for (int k = 0; k < 4; k++) acc[i][j][k] = 0.f;

    const int lrow = lane & 15, lcol8 = (lane >> 4) << 3;

    oproj_load(Ah, Bh, 0, m0, n0b, 0, tid);
    CP_COMMIT;

    const int NT = DD / 64;
    for (int it = 0; it < NT; it++) {
        int p = it & 1;
        if (it + 1 < NT) {
            oproj_load(Ah, Bh, (it+1)&1, m0, n0b, (it+1)*64, tid);
            CP_COMMIT;
            CP_WAIT1;
        } else {
            CP_WAIT0;
        }
        __syncthreads();

        __half* Ahp = Ah + p * (128*OP_LDA);
        __half* Bhp = Bh + p * (64*OP_LDB);

        #pragma unroll
        for (int ks = 0; ks < 4; ks++) {
            int k0 = ks * 16;
            unsigned ah[2][4];
            #pragma unroll
            for (int mf = 0; mf < 2; mf++) {
                int row = wm * 32 + mf * 16 + lrow;
                ldsm4(ah[mf], su32(Ahp + row * OP_LDA + k0 + lcol8));
            }
            #pragma unroll
            for (int nf2 = 0; nf2 < 4; nf2++) {
                unsigned bh[4];
                int n0 = wn * 64 + nf2 * 16;
                ldsm4t(bh, su32(Bhp + (k0 + lrow) * OP_LDB + n0 + lcol8));
                #pragma unroll
                for (int hn = 0; hn < 2; hn++) {
                    #pragma unroll
                    for (int mf = 0; mf < 2; mf++)
                        mma16816(acc[mf][nf2*2 + hn], ah[mf], bh + hn*2);
                }
            }
        }
        __syncthreads();
    }

    #pragma unroll
    for (int mf = 0; mf < 2; mf++) {
        #pragma unroll
        for (int nf = 0; nf < 8; nf++) {
            int col = n0b + wn * 64 + nf * 8 + (lane & 3) * 2;
            float b0 = bo[col], b1 = bo[col + 1];
            #pragma unroll
            for (int hr = 0; hr < 2; hr++) {
                int m = m0 + wm * 32 + mf * 16 + (lane >> 2) + hr * 8;
                float2 v = make_float2(acc[mf][nf][hr*2+0] + b0,
                                       acc[mf][nf][hr*2+1] + b1);
                *(float2*)(out + (size_t)m * DD + col) = v;
            }
        }
    }
}

// ---------------------------------------------------------------------------
extern "C" void kernel_launch(void* const* d_in, const int* in_sizes, int n_in,
                              void* d_out, int out_size)
{
    (void)in_sizes; (void)n_in; (void)out_size;
    const float* Xq = (const float*)d_in[0];
    const float* Xk = (const float*)d_in[1];
    const float* Xv = (const float*)d_in[2];
    const float* Wq = (const float*)d_in[3];
    const float* bq = (const float*)d_in[4];
    const float* Wk = (const float*)d_in[5];
    const float* bk = (const float*)d_in[6];
    const float* Wv = (const float*)d_in[7];
    const float* bv = (const float*)d_in[8];
    const float* Wo = (const float*)d_in[9];
    const float* bo = (const float*)d_in[10];
    float* out = (float*)d_out;

    const int total4 = 3*NX4 + 4*NW4;
    convert_all<<<(total4 + 255) / 256, 256>>>(Xq, Xk, Xv, Wq, Wk, Wv, Wo);

    const int smem_qkv = (2*128*QK_LDA + 2*64*QK_LDB) * (int)sizeof(__half);   // 63488
    cudaFuncSetAttribute(qkv_kernel, cudaFuncAttributeMaxDynamicSharedMemorySize, smem_qkv);
    dim3 gq(MM / 128, HH, 3);
    qkv_kernel<<<gq, 256, smem_qkv>>>(bq, bk, bv);

    const int smem_attn = 3 * KV_REG * (int)sizeof(__half);                    // 79872
    cudaFuncSetAttribute(attn_kernel, cudaFuncAttributeMaxDynamicSharedMemorySize, smem_attn);
    dim3 ga(SS / 256, HH, BB);   // 256 blocks -> single wave at 2/SM
    attn_kernel<<<ga, 256, smem_attn>>>();

    const int smem_op = (2*128*OP_LDA + 2*64*OP_LDB) * (int)sizeof(__half);    // 71680
    cudaFuncSetAttribute(oproj_kernel, cudaFuncAttributeMaxDynamicSharedMemorySize, smem_op);
    dim3 go(MM / 128, DD / 128);
    oproj_kernel<<<go, 256, smem_op>>>(bo, out);
}

// round 16
// speedup vs baseline: 1.5659x; 1.0303x over previous
#include <cuda_runtime.h>
#include <cuda_fp16.h>

#define BB 4
#define SS 2048
#define DD 768
#define HH 8
#define DHH 96
#define MM (BB*SS)   // 8192

// Pure fp16 scratch (fp32 accumulate in mma)
__device__ __half g_Xqh[(size_t)MM*DD];
__device__ __half g_Xkh[(size_t)MM*DD];
__device__ __half g_Xvh[(size_t)MM*DD];
__device__ __half g_Wqh[(size_t)HH*DD*DHH];
__device__ __half g_Wkh[(size_t)HH*DD*DHH];
__device__ __half g_Wvh[(size_t)HH*DD*DHH];
__device__ __half g_Woh[(size_t)DD*DD];
__device__ __half g_Qh[(size_t)BB*HH*SS*DHH];   // pre-scaled by log2e/sqrt(96)
__device__ __half g_Kh[(size_t)BB*HH*SS*DHH];
__device__ __half g_Vh[(size_t)BB*HH*SS*DHH];
__device__ __half g_cath[(size_t)MM*DD];

__device__ __forceinline__ unsigned su32(const void* p) {
    return (unsigned)__cvta_generic_to_shared(p);
}
// packed fp32x2 -> fp16x2 (lo in low half)
__device__ __forceinline__ unsigned cvt2h(float lo, float hi) {
    unsigned r;
    asm("cvt.rn.f16x2.f32 %0, %1, %2;" : "=r"(r) : "f"(hi), "f"(lo));
    return r;
}
// raw single-MUFU exp2 (args are <= 0 here; approx error ~2^-22)
__device__ __forceinline__ float ex2(float x) {
    float r;
    asm("ex2.approx.ftz.f32 %0, %1;" : "=f"(r) : "f"(x));
    return r;
}
__device__ __forceinline__ void ldsm4(unsigned r[4], unsigned addr) {
    asm volatile("ldmatrix.sync.aligned.m8n8.x4.shared.b16 {%0,%1,%2,%3},[%4];\n"
        : "=r"(r[0]), "=r"(r[1]), "=r"(r[2]), "=r"(r[3]) : "r"(addr));
}
__device__ __forceinline__ void ldsm4t(unsigned r[4], unsigned addr) {
    asm volatile("ldmatrix.sync.aligned.m8n8.x4.trans.shared.b16 {%0,%1,%2,%3},[%4];\n"
        : "=r"(r[0]), "=r"(r[1]), "=r"(r[2]), "=r"(r[3]) : "r"(addr));
}
__device__ __forceinline__ void mma16816(float* c, const unsigned* a, const unsigned* b) {
    asm volatile("mma.sync.aligned.m16n8k16.row.col.f32.f16.f16.f32 "
        "{%0,%1,%2,%3},{%4,%5,%6,%7},{%8,%9},{%0,%1,%2,%3};\n"
        : "+f"(c[0]), "+f"(c[1]), "+f"(c[2]), "+f"(c[3])
        : "r"(a[0]), "r"(a[1]), "r"(a[2]), "r"(a[3]), "r"(b[0]), "r"(b[1]));
}
#define CPA(dst, src) asm volatile("cp.async.cg.shared.global [%0], [%1], 16;\n" :: "r"(dst), "l"(src))
#define CP_COMMIT asm volatile("cp.async.commit_group;\n")
#define CP_WAIT2  asm volatile("cp.async.wait_group 2;\n")
#define CP_WAIT1  asm volatile("cp.async.wait_group 1;\n")
#define CP_WAIT0  asm volatile("cp.async.wait_group 0;\n")

// ---------------------------------------------------------------------------
// Preconvert fp32 -> fp16 (all 7 tensors, one launch)
// ---------------------------------------------------------------------------
#define NX4 (MM*DD/4)          // 1572864
#define NW4 (HH*DD*DHH/4)      // 147456

__global__ __launch_bounds__(256) void convert_all(
    const float* __restrict__ Xq, const float* __restrict__ Xk, const float* __restrict__ Xv,
    const float* __restrict__ Wq, const float* __restrict__ Wk, const float* __restrict__ Wv,
    const float* __restrict__ Wo)
{
    int i = blockIdx.x * 256 + threadIdx.x;
    const float* src; __half* dh; int off;
    if (i < 3 * NX4) {
        int t = i / NX4; off = i - t * NX4;
        src = (t == 0) ? Xq : (t == 1) ? Xk : Xv;
        dh  = (t == 0) ? g_Xqh : (t == 1) ? g_Xkh : g_Xvh;
    } else {
        int j = i - 3 * NX4;
        if (j >= 4 * NW4) return;
        int t = j / NW4; off = j - t * NW4;
        src = (t == 0) ? Wq : (t == 1) ? Wk : (t == 2) ? Wv : Wo;
        dh  = (t == 0) ? g_Wqh : (t == 1) ? g_Wkh : (t == 2) ? g_Wvh : g_Woh;
    }
    float4 v = ((const float4*)src)[off];
    uint2 u;
    u.x = cvt2h(v.x, v.y);
    u.y = cvt2h(v.z, v.w);
    ((uint2*)dh)[off] = u;
}

// ---------------------------------------------------------------------------
// QKV GEMM (fp16, fp32 accum). BM=128, BN=96, BK=64, 2-stage cp.async.
// Q pre-scaled by log2e/sqrt(96). grid=(64, 8, 3).
// ---------------------------------------------------------------------------
#define QK_LDA 72
#define QK_LDB 104

__device__ __forceinline__ void qkv_load(
    __half* Ah, __half* Bh,
    const __half* gXh, const __half* gWh,
    int p, int m0, int kt, size_t wbase, int tid)
{
    #pragma unroll
    for (int j = 0; j < 7; j++) {
        int c = tid + j * 256;             // 0..1791
        if (c < 1024) {
            int row = c >> 3, off = (c & 7) * 8;
            CPA(su32(Ah + p * (128*QK_LDA) + row * QK_LDA + off),
                gXh + (size_t)(m0 + row) * DD + kt + off);
        } else {
            int c2 = c - 1024;             // 0..767
            int row = c2 / 12, off = (c2 - row * 12) * 8;
            CPA(su32(Bh + p * (64*QK_LDB) + row * QK_LDB + off),
                gWh + wbase + (size_t)(kt + row) * DHH + off);
        }
    }
}

__global__ __launch_bounds__(256, 2) void qkv_kernel(
    const float* __restrict__ bq, const float* __restrict__ bk, const float* __restrict__ bv)
{
    extern __shared__ __half smq[];
    __half* Ah = smq;                      // 2 x 128 x 72
    __half* Bh = Ah + 2*128*QK_LDA;        // 2 x 64 x 104

    const __half *gXh, *gWh; const float* bias; __half *oh;
    if (blockIdx.z == 0)      { gXh=g_Xqh; gWh=g_Wqh; bias=bq; oh=g_Qh; }
    else if (blockIdx.z == 1) { gXh=g_Xkh; gWh=g_Wkh; bias=bk; oh=g_Kh; }
    else                      { gXh=g_Xvh; gWh=g_Wvh; bias=bv; oh=g_Vh; }
    const float oscale = (blockIdx.z == 0) ? rsqrtf(96.0f) * 1.4426950408889634f : 1.0f;

    const int h   = blockIdx.y;
    const int m0  = blockIdx.x * 128;
    const int tid = threadIdx.x;
    const int wid = tid >> 5, lane = tid & 31;
    const int wm  = wid >> 1, wn = wid & 1;
    const size_t wbase = (size_t)h * DD * DHH;

    float acc[2][6][4];
    #pragma unroll
    for (int i = 0; i < 2; i++)
        #pragma unroll
        for (int j = 0; j < 6; j++)
            #pragma unroll
            for (int k = 0; k < 4; k++) acc[i][j][k] = 0.f;

    const int lrow = lane & 15, lcol8 = (lane >> 4) << 3;

    qkv_load(Ah, Bh, gXh, gWh, 0, m0, 0, wbase, tid);
    CP_COMMIT;

    const int NT = DD / 64;   // 12
    for (int it = 0; it < NT; it++) {
        int p = it & 1;
        if (it + 1 < NT) {
            qkv_load(Ah, Bh, gXh, gWh, (it+1)&1, m0, (it+1)*64, wbase, tid);
            CP_COMMIT;
            CP_WAIT1;
        } else {
            CP_WAIT0;
        }
        __syncthreads();

        __half* Ahp = Ah + p * (128*QK_LDA);
        __half* Bhp = Bh + p * (64*QK_LDB);

        #pragma unroll
        for (int ks = 0; ks < 4; ks++) {
            int k0 = ks * 16;
            unsigned ah[2][4];
            #pragma unroll
            for (int mf = 0; mf < 2; mf++) {
                int row = wm * 32 + mf * 16 + lrow;
                ldsm4(ah[mf], su32(Ahp + row * QK_LDA + k0 + lcol8));
            }
            #pragma unroll
            for (int nf2 = 0; nf2 < 3; nf2++) {
                unsigned bh[4];
                int n0 = wn * 48 + nf2 * 16;
                ldsm4t(bh, su32(Bhp + (k0 + lrow) * QK_LDB + n0 + lcol8));
                #pragma unroll
                for (int hn = 0; hn < 2; hn++) {
                    #pragma unroll
                    for (int mf = 0; mf < 2; mf++)
                        mma16816(acc[mf][nf2*2 + hn], ah[mf], bh + hn*2);
                }
            }
        }
        __syncthreads();
    }

    #pragma unroll
    for (int mf = 0; mf < 2; mf++) {
        #pragma unroll
        for (int nf = 0; nf < 6; nf++) {
            int col = wn * 48 + nf * 8 + (lane & 3) * 2;
            float b0 = bias[h*DHH + col], b1 = bias[h*DHH + col + 1];
            #pragma unroll
            for (int hr = 0; hr < 2; hr++) {
                int m = m0 + wm * 32 + mf * 16 + (lane >> 2) + hr * 8;
                int bb = m >> 11, s = m & 2047;
                size_t off = (((size_t)(bb * HH + h)) * SS + s) * DHH + col;
                float v0 = (acc[mf][nf][hr*2 + 0] + b0) * oscale;
                float v1 = (acc[mf][nf][hr*2 + 1] + b1) * oscale;
                *(unsigned*)(oh + off) = cvt2h(v0, v1);
            }
        }
    }
}

// ---------------------------------------------------------------------------
// Flash attention, fp16 mma, 3-region KV pipeline, base-2 softmax (raw ex2),
// conditional accumulator rescale (skips when no new row-max in warp).
// grid=(8,8,4): 256 blocks, 2 sequential Q-chunks per block.
// ---------------------------------------------------------------------------
#define AT_LD 104
#define KV_REG (2*64*AT_LD)

__device__ __forceinline__ void attn_load_kv(__half* Kbuf, size_t gbase, int tid)
{
    __half* Vbuf = Kbuf + 64 * AT_LD;
    #pragma unroll
    for (int j = 0; j < 6; j++) {
        int c = tid + j * 256;
        int arr = (c >= 768) ? 1 : 0;
        int rem = c - arr * 768;
        int row = rem / 12;
        int off = (rem - row * 12) * 8;
        const __half* sp = (arr ? g_Vh : g_Kh) + (gbase + row) * DHH + off;
        __half* dp = (arr ? Vbuf : Kbuf) + row * AT_LD + off;
        CPA(su32(dp), sp);
    }
}

__global__ __launch_bounds__(256, 2) void attn_kernel()
{
    extern __shared__ __half smh[];
    __half* R0 = smh;
    __half* R1 = smh + KV_REG;
    __half* R2 = smh + 2 * KV_REG;

    const int b  = blockIdx.z, h = blockIdx.y;
    const int tid = threadIdx.x, wid = tid >> 5, lane = tid & 31;
    const size_t base = ((size_t)(b * HH + h)) * SS;

    const int lrow = lane & 15, lcol8 = (lane >> 4) << 3;
    const int krow_off = (lane & 7) + ((lane & 16) >> 1);
    const int kcol_off = (lane & 8);
    const int NT = SS / 64;   // 32

    for (int qc = 0; qc < 2; qc++) {
        const int s0 = blockIdx.x * 256 + qc * 128;

        {   // load Q chunk into region 0
            int r = tid >> 1, c0 = (tid & 1) * 48;
            size_t go = (base + s0 + r) * DHH + c0;
            __half* dh = R0 + r * AT_LD + c0;
            #pragma unroll
            for (int i = 0; i < 6; i++)
                *(uint4*)(dh + i*8) = *(const uint4*)(g_Qh + go + i*8);
        }

        attn_load_kv(R1, base, tid);      CP_COMMIT;
        attn_load_kv(R2, base + 64, tid); CP_COMMIT;

        __syncthreads();   // Q ready
        unsigned qf[6][4];
        {
            int qrow = wid * 16 + lrow;
            #pragma unroll
            for (int dk = 0; dk < 6; dk++)
                ldsm4(qf[dk], su32(R0 + qrow * AT_LD + dk * 16 + lcol8));
        }
        __syncthreads();   // region 0 reusable

        attn_load_kv(R0, base + 128, tid); CP_COMMIT;

        float oacc[12][4];
        #pragma unroll
        for (int j = 0; j < 12; j++)
            #pragma unroll
            for (int t = 0; t < 4; t++) oacc[j][t] = 0.f;
        float m0r = -1e30f, m1r = -1e30f, l0r = 0.f, l1r = 0.f;

        int cur = 1;
        for (int it = 0; it < NT; it++) {
            if (it < NT - 2)      { CP_WAIT2; }
            else if (it == NT - 2){ CP_WAIT1; }
            else                  { CP_WAIT0; }
            __syncthreads();

            __half* Kp = smh + cur * KV_REG;
            __half* Vp = Kp + 64 * AT_LD;

            // S = Q @ K^T (log2 domain)
            float sacc[8][4];
            #pragma unroll
            for (int j = 0; j < 8; j++)
                #pragma unroll
                for (int t = 0; t < 4; t++) sacc[j][t] = 0.f;

            #pragma unroll
            for (int dk = 0; dk < 6; dk++) {
                int d0 = dk * 16;
                #pragma unroll
                for (int nf2 = 0; nf2 < 4; nf2++) {
                    unsigned bh[4];
                    ldsm4(bh, su32(Kp + (nf2 * 16 + krow_off) * AT_LD + d0 + kcol_off));
                    mma16816(sacc[nf2*2 + 0], qf[dk], bh + 0);
                    mma16816(sacc[nf2*2 + 1], qf[dk], bh + 2);
                }
            }

            // online softmax (base-2, raw MUFU ex2)
            float mx0 = -1e30f, mx1 = -1e30f;
            #pragma unroll
            for (int j = 0; j < 8; j++) {
                mx0 = fmaxf(mx0, fmaxf(sacc[j][0], sacc[j][1]));
                mx1 = fmaxf(mx1, fmaxf(sacc[j][2], sacc[j][3]));
            }
            mx0 = fmaxf(mx0, __shfl_xor_sync(0xffffffffu, mx0, 1));
            mx0 = fmaxf(mx0, __shfl_xor_sync(0xffffffffu, mx0, 2));
            mx1 = fmaxf(mx1, __shfl_xor_sync(0xffffffffu, mx1, 1));
            mx1 = fmaxf(mx1, __shfl_xor_sync(0xffffffffu, mx1, 2));

            // Rescale only when a new row-max appears (warp-uniform skip).
            if (__any_sync(0xffffffffu, (mx0 > m0r) | (mx1 > m1r))) {
                float mn0 = fmaxf(m0r, mx0), mn1 = fmaxf(m1r, mx1);
                float corr0 = ex2(m0r - mn0), corr1 = ex2(m1r - mn1);
                m0r = mn0; m1r = mn1;
                l0r *= corr0; l1r *= corr1;
                #pragma unroll
                for (int j = 0; j < 12; j++) {
                    oacc[j][0] *= corr0; oacc[j][1] *= corr0;
                    oacc[j][2] *= corr1; oacc[j][3] *= corr1;
                }
            }

            float sum0 = 0.f, sum1 = 0.f;
            #pragma unroll
            for (int j = 0; j < 8; j++) {
                sacc[j][0] = ex2(sacc[j][0] - m0r);
                sacc[j][1] = ex2(sacc[j][1] - m0r);
                sacc[j][2] = ex2(sacc[j][2] - m1r);
                sacc[j][3] = ex2(sacc[j][3] - m1r);
                sum0 += sacc[j][0] + sacc[j][1];
                sum1 += sacc[j][2] + sacc[j][3];
            }
            sum0 += __shfl_xor_sync(0xffffffffu, sum0, 1);
            sum0 += __shfl_xor_sync(0xffffffffu, sum0, 2);
            sum1 += __shfl_xor_sync(0xffffffffu, sum1, 1);
            sum1 += __shfl_xor_sync(0xffffffffu, sum1, 2);
            l0r += sum0;
            l1r += sum1;

            // P fragments (packed cvt)
            unsigned ph[4][4];
            #pragma unroll
            for (int kf = 0; kf < 4; kf++) {
                #pragma unroll
                for (int q = 0; q < 4; q++) {
                    int fj = kf*2 + (q >> 1);
                    int t0 = (q & 1) * 2;
                    ph[kf][q] = cvt2h(sacc[fj][t0], sacc[fj][t0 + 1]);
                }
            }

            // O += P @ V
            #pragma unroll
            for (int kf = 0; kf < 4; kf++) {
                int k0 = kf * 16;
                #pragma unroll
                for (int nf2 = 0; nf2 < 6; nf2++) {
                    unsigned bh[4];
                    ldsm4t(bh, su32(Vp + (k0 + lrow) * AT_LD + nf2 * 16 + lcol8));
                    mma16816(oacc[nf2*2 + 0], ph[kf], bh + 0);
                    mma16816(oacc[nf2*2 + 1], ph[kf], bh + 2);
                }
            }
            __syncthreads();
            if (it + 3 < NT) {
                attn_load_kv(Kp, base + (size_t)(it + 3) * 64, tid);
                CP_COMMIT;
            }
            cur = (cur == 2) ? 0 : cur + 1;
        }

        // Epilogue
        float inv0 = 1.0f / l0r, inv1 = 1.0f / l1r;
        #pragma unroll
        for (int nf = 0; nf < 12; nf++) {
            int col = h * DHH + nf * 8 + (lane & 3) * 2;
            #pragma unroll
            for (int hr = 0; hr < 2; hr++) {
                int s = s0 + wid * 16 + (lane >> 2) + hr * 8;
                size_t off = ((size_t)b * SS + s) * DD + col;
                float inv = hr ? inv1 : inv0;
                *(unsigned*)(g_cath + off) =
                    cvt2h(oacc[nf][hr*2 + 0] * inv, oacc[nf][hr*2 + 1] * inv);
            }
        }
        __syncthreads();   // drain before next chunk reuses regions
    }
}

// ---------------------------------------------------------------------------
// Output projection (fp16): out = cath @ Woh + bo. BM=128, BN=128, BK=64.
// ---------------------------------------------------------------------------
#define OP_LDA 72
#define OP_LDB 136

__device__ __forceinline__ void oproj_load(
    __half* Ah, __half* Bh, int p, int m0, int n0b, int kt, int tid)
{
    #pragma unroll
    for (int j = 0; j < 8; j++) {
        int c = tid + j * 256;
        if (c < 1024) {
            int row = c >> 3, off = (c & 7) * 8;
            CPA(su32(Ah + p * (128*OP_LDA) + row * OP_LDA + off),
                g_cath + (size_t)(m0 + row) * DD + kt + off);
        } else {
            int c2 = c - 1024;
            int row = c2 >> 4, off = (c2 & 15) * 8;
            CPA(su32(Bh + p * (64*OP_LDB) + row * OP_LDB + off),
                g_Woh + (size_t)(kt + row) * DD + n0b + off);
        }
    }
}

__global__ __launch_bounds__(256, 2) void oproj_kernel(
    const float* __restrict__ bo, float* __restrict__ out)
{
    extern __shared__ __half smo[];
    __half* Ah = smo;
    __half* Bh = Ah + 2*128*OP_LDA;

    const int m0  = blockIdx.x * 128;
    const int n0b = blockIdx.y * 128;
    const int tid = threadIdx.x, wid = tid >> 5, lane = tid & 31;
    const int wm = wid >> 1, wn = wid & 1;

    float acc[2][8][4];
    #pragma unroll
    for (int i = 0; i < 2; i++)
        #pragma unroll
        for (int j = 0; j < 8; j++)
            #pragma unroll
            for (int k = 0; k < 4; k++) acc[i][j][k] = 0.f;

    const int lrow = lane & 15, lcol8 = (lane >> 4) << 3;

    oproj_load(Ah, Bh, 0, m0, n0b, 0, tid);
    CP_COMMIT;

    const int NT = DD / 64;
    for (int it = 0; it < NT; it++) {
        int p = it & 1;
        if (it + 1 < NT) {
            oproj_load(Ah, Bh, (it+1)&1, m0, n0b, (it+1)*64, tid);
            CP_COMMIT;
            CP_WAIT1;
        } else {
            CP_WAIT0;
        }
        __syncthreads();

        __half* Ahp = Ah + p * (128*OP_LDA);
        __half* Bhp = Bh + p * (64*OP_LDB);

        #pragma unroll
        for (int ks = 0; ks < 4; ks++) {
            int k0 = ks * 16;
            unsigned ah[2][4];
            #pragma unroll
            for (int mf = 0; mf < 2; mf++) {
                int row = wm * 32 + mf * 16 + lrow;
                ldsm4(ah[mf], su32(Ahp + row * OP_LDA + k0 + lcol8));
            }
            #pragma unroll
            for (int nf2 = 0; nf2 < 4; nf2++) {
                unsigned bh[4];
                int n0 = wn * 64 + nf2 * 16;
                ldsm4t(bh, su32(Bhp + (k0 + lrow) * OP_LDB + n0 + lcol8));
                #pragma unroll
                for (int hn = 0; hn < 2; hn++) {
                    #pragma unroll
                    for (int mf = 0; mf < 2; mf++)
                        mma16816(acc[mf][nf2*2 + hn], ah[mf], bh + hn*2);
                }
            }
        }
        __syncthreads();
    }

    #pragma unroll
    for (int mf = 0; mf < 2; mf++) {
        #pragma unroll
        for (int nf = 0; nf < 8; nf++) {
            int col = n0b + wn * 64 + nf * 8 + (lane & 3) * 2;
            float b0 = bo[col], b1 = bo[col + 1];
            #pragma unroll
            for (int hr = 0; hr < 2; hr++) {
                int m = m0 + wm * 32 + mf * 16 + (lane >> 2) + hr * 8;
                float2 v = make_float2(acc[mf][nf][hr*2+0] + b0,
                                       acc[mf][nf][hr*2+1] + b1);
                *(float2*)(out + (size_t)m * DD + col) = v;
            }
        }
    }
}

// ---------------------------------------------------------------------------
extern "C" void kernel_launch(void* const* d_in, const int* in_sizes, int n_in,
                              void* d_out, int out_size)
{
    (void)in_sizes; (void)n_in; (void)out_size;
    const float* Xq = (const float*)d_in[0];
    const float* Xk = (const float*)d_in[1];
    const float* Xv = (const float*)d_in[2];
    const float* Wq = (const float*)d_in[3];
    const float* bq = (const float*)d_in[4];
    const float* Wk = (const float*)d_in[5];
    const float* bk = (const float*)d_in[6];
    const float* Wv = (const float*)d_in[7];
    const float* bv = (const float*)d_in[8];
    const float* Wo = (const float*)d_in[9];
    const float* bo = (const float*)d_in[10];
    float* out = (float*)d_out;

    const int total4 = 3*NX4 + 4*NW4;
    convert_all<<<(total4 + 255) / 256, 256>>>(Xq, Xk, Xv, Wq, Wk, Wv, Wo);

    const int smem_qkv = (2*128*QK_LDA + 2*64*QK_LDB) * (int)sizeof(__half);   // 63488
    cudaFuncSetAttribute(qkv_kernel, cudaFuncAttributeMaxDynamicSharedMemorySize, smem_qkv);
    dim3 gq(MM / 128, HH, 3);
    qkv_kernel<<<gq, 256, smem_qkv>>>(bq, bk, bv);

    const int smem_attn = 3 * KV_REG * (int)sizeof(__half);                    // 79872
    cudaFuncSetAttribute(attn_kernel, cudaFuncAttributeMaxDynamicSharedMemorySize, smem_attn);
    dim3 ga(SS / 256, HH, BB);
    attn_kernel<<<ga, 256, smem_attn>>>();

    const int smem_op = (2*128*OP_LDA + 2*64*OP_LDB) * (int)sizeof(__half);    // 71680
    cudaFuncSetAttribute(oproj_kernel, cudaFuncAttributeMaxDynamicSharedMemorySize, smem_op);
    dim3 go(MM / 128, DD / 128);
    oproj_kernel<<<go, 256, smem_op>>>(bo, out);
}

// round 17
// speedup vs baseline: 1.5838x; 1.0114x over previous
#include <cuda_runtime.h>
#include <cuda_fp16.h>

#define BB 4
#define SS 2048
#define DD 768
#define HH 8
#define DHH 96
#define MM (BB*SS)   // 8192

// Pure fp16 scratch (fp32 accumulate in mma)
__device__ __half g_Xqh[(size_t)MM*DD];
__device__ __half g_Xkh[(size_t)MM*DD];
__device__ __half g_Xvh[(size_t)MM*DD];
__device__ __half g_Wqh[(size_t)HH*DD*DHH];
__device__ __half g_Wkh[(size_t)HH*DD*DHH];
__device__ __half g_Wvh[(size_t)HH*DD*DHH];
__device__ __half g_Woh[(size_t)DD*DD];
__device__ __half g_Qh[(size_t)BB*HH*SS*DHH];   // pre-scaled by log2e/sqrt(96)
__device__ __half g_Kh[(size_t)BB*HH*SS*DHH];
__device__ __half g_Vh[(size_t)BB*HH*SS*DHH];
__device__ __half g_cath[(size_t)MM*DD];

__device__ __forceinline__ unsigned su32(const void* p) {
    return (unsigned)__cvta_generic_to_shared(p);
}
// packed fp32x2 -> fp16x2 (lo in low half)
__device__ __forceinline__ unsigned cvt2h(float lo, float hi) {
    unsigned r;
    asm("cvt.rn.f16x2.f32 %0, %1, %2;" : "=r"(r) : "f"(hi), "f"(lo));
    return r;
}
// raw single-MUFU exp2 fp32
__device__ __forceinline__ float ex2(float x) {
    float r;
    asm("ex2.approx.ftz.f32 %0, %1;" : "=f"(r) : "f"(x));
    return r;
}
// packed fp16x2 exp2 (one MUFU for two values)
__device__ __forceinline__ unsigned ex2h2(unsigned x) {
    unsigned r;
    asm("ex2.approx.f16x2 %0, %1;" : "=r"(r) : "r"(x));
    return r;
}
__device__ __forceinline__ void ldsm4(unsigned r[4], unsigned addr) {
    asm volatile("ldmatrix.sync.aligned.m8n8.x4.shared.b16 {%0,%1,%2,%3},[%4];\n"
        : "=r"(r[0]), "=r"(r[1]), "=r"(r[2]), "=r"(r[3]) : "r"(addr));
}
__device__ __forceinline__ void ldsm4t(unsigned r[4], unsigned addr) {
    asm volatile("ldmatrix.sync.aligned.m8n8.x4.trans.shared.b16 {%0,%1,%2,%3},[%4];\n"
        : "=r"(r[0]), "=r"(r[1]), "=r"(r[2]), "=r"(r[3]) : "r"(addr));
}
__device__ __forceinline__ void mma16816(float* c, const unsigned* a, const unsigned* b) {
    asm volatile("mma.sync.aligned.m16n8k16.row.col.f32.f16.f16.f32 "
        "{%0,%1,%2,%3},{%4,%5,%6,%7},{%8,%9},{%0,%1,%2,%3};\n"
        : "+f"(c[0]), "+f"(c[1]), "+f"(c[2]), "+f"(c[3])
        : "r"(a[0]), "r"(a[1]), "r"(a[2]), "r"(a[3]), "r"(b[0]), "r"(b[1]));
}
#define CPA(dst, src) asm volatile("cp.async.cg.shared.global [%0], [%1], 16;\n" :: "r"(dst), "l"(src))
#define CP_COMMIT asm volatile("cp.async.commit_group;\n")
#define CP_WAIT2  asm volatile("cp.async.wait_group 2;\n")
#define CP_WAIT1  asm volatile("cp.async.wait_group 1;\n")
#define CP_WAIT0  asm volatile("cp.async.wait_group 0;\n")

// ---------------------------------------------------------------------------
// Preconvert fp32 -> fp16 (all 7 tensors, one launch)
// ---------------------------------------------------------------------------
#define NX4 (MM*DD/4)          // 1572864
#define NW4 (HH*DD*DHH/4)      // 147456

__global__ __launch_bounds__(256) void convert_all(
    const float* __restrict__ Xq, const float* __restrict__ Xk, const float* __restrict__ Xv,
    const float* __restrict__ Wq, const float* __restrict__ Wk, const float* __restrict__ Wv,
    const float* __restrict__ Wo)
{
    int i = blockIdx.x * 256 + threadIdx.x;
    const float* src; __half* dh; int off;
    if (i < 3 * NX4) {
        int t = i / NX4; off = i - t * NX4;
        src = (t == 0) ? Xq : (t == 1) ? Xk : Xv;
        dh  = (t == 0) ? g_Xqh : (t == 1) ? g_Xkh : g_Xvh;
    } else {
        int j = i - 3 * NX4;
        if (j >= 4 * NW4) return;
        int t = j / NW4; off = j - t * NW4;
        src = (t == 0) ? Wq : (t == 1) ? Wk : (t == 2) ? Wv : Wo;
        dh  = (t == 0) ? g_Wqh : (t == 1) ? g_Wkh : (t == 2) ? g_Wvh : g_Woh;
    }
    float4 v = ((const float4*)src)[off];
    uint2 u;
    u.x = cvt2h(v.x, v.y);
    u.y = cvt2h(v.z, v.w);
    ((uint2*)dh)[off] = u;
}

// ---------------------------------------------------------------------------
// QKV GEMM (fp16, fp32 accum). BM=128, BN=96, BK=64, 2-stage cp.async.
// Q pre-scaled by log2e/sqrt(96). grid=(64, 8, 3).
// ---------------------------------------------------------------------------
#define QK_LDA 72
#define QK_LDB 104

__device__ __forceinline__ void qkv_load(
    __half* Ah, __half* Bh,
    const __half* gXh, const __half* gWh,
    int p, int m0, int kt, size_t wbase, int tid)
{
    #pragma unroll
    for (int j = 0; j < 7; j++) {
        int c = tid + j * 256;             // 0..1791
        if (c < 1024) {
            int row = c >> 3, off = (c & 7) * 8;
            CPA(su32(Ah + p * (128*QK_LDA) + row * QK_LDA + off),
                gXh + (size_t)(m0 + row) * DD + kt + off);
        } else {
            int c2 = c - 1024;             // 0..767
            int row = c2 / 12, off = (c2 - row * 12) * 8;
            CPA(su32(Bh + p * (64*QK_LDB) + row * QK_LDB + off),
                gWh + wbase + (size_t)(kt + row) * DHH + off);
        }
    }
}

__global__ __launch_bounds__(256, 2) void qkv_kernel(
    const float* __restrict__ bq, const float* __restrict__ bk, const float* __restrict__ bv)
{
    extern __shared__ __half smq[];
    __half* Ah = smq;                      // 2 x 128 x 72
    __half* Bh = Ah + 2*128*QK_LDA;        // 2 x 64 x 104

    const __half *gXh, *gWh; const float* bias; __half *oh;
    if (blockIdx.z == 0)      { gXh=g_Xqh; gWh=g_Wqh; bias=bq; oh=g_Qh; }
    else if (blockIdx.z == 1) { gXh=g_Xkh; gWh=g_Wkh; bias=bk; oh=g_Kh; }
    else                      { gXh=g_Xvh; gWh=g_Wvh; bias=bv; oh=g_Vh; }
    const float oscale = (blockIdx.z == 0) ? rsqrtf(96.0f) * 1.4426950408889634f : 1.0f;

    const int h   = blockIdx.y;
    const int m0  = blockIdx.x * 128;
    const int tid = threadIdx.x;
    const int wid = tid >> 5, lane = tid & 31;
    const int wm  = wid >> 1, wn = wid & 1;
    const size_t wbase = (size_t)h * DD * DHH;

    float acc[2][6][4];
    #pragma unroll
    for (int i = 0; i < 2; i++)
        #pragma unroll
        for (int j = 0; j < 6; j++)
            #pragma unroll
            for (int k = 0; k < 4; k++) acc[i][j][k] = 0.f;

    const int lrow = lane & 15, lcol8 = (lane >> 4) << 3;

    qkv_load(Ah, Bh, gXh, gWh, 0, m0, 0, wbase, tid);
    CP_COMMIT;

    const int NT = DD / 64;   // 12
    for (int it = 0; it < NT; it++) {
        int p = it & 1;
        if (it + 1 < NT) {
            qkv_load(Ah, Bh, gXh, gWh, (it+1)&1, m0, (it+1)*64, wbase, tid);
            CP_COMMIT;
            CP_WAIT1;
        } else {
            CP_WAIT0;
        }
        __syncthreads();

        __half* Ahp = Ah + p * (128*QK_LDA);
        __half* Bhp = Bh + p * (64*QK_LDB);

        #pragma unroll
        for (int ks = 0; ks < 4; ks++) {
            int k0 = ks * 16;
            unsigned ah[2][4];
            #pragma unroll
            for (int mf = 0; mf < 2; mf++) {
                int row = wm * 32 + mf * 16 + lrow;
                ldsm4(ah[mf], su32(Ahp + row * QK_LDA + k0 + lcol8));
            }
            #pragma unroll
            for (int nf2 = 0; nf2 < 3; nf2++) {
                unsigned bh[4];
                int n0 = wn * 48 + nf2 * 16;
                ldsm4t(bh, su32(Bhp + (k0 + lrow) * QK_LDB + n0 + lcol8));
                #pragma unroll
                for (int hn = 0; hn < 2; hn++) {
                    #pragma unroll
                    for (int mf = 0; mf < 2; mf++)
                        mma16816(acc[mf][nf2*2 + hn], ah[mf], bh + hn*2);
                }
            }
        }
        __syncthreads();
    }

    #pragma unroll
    for (int mf = 0; mf < 2; mf++) {
        #pragma unroll
        for (int nf = 0; nf < 6; nf++) {
            int col = wn * 48 + nf * 8 + (lane & 3) * 2;
            float b0 = bias[h*DHH + col], b1 = bias[h*DHH + col + 1];
            #pragma unroll
            for (int hr = 0; hr < 2; hr++) {
                int m = m0 + wm * 32 + mf * 16 + (lane >> 2) + hr * 8;
                int bb = m >> 11, s = m & 2047;
                size_t off = (((size_t)(bb * HH + h)) * SS + s) * DHH + col;
                float v0 = (acc[mf][nf][hr*2 + 0] + b0) * oscale;
                float v1 = (acc[mf][nf][hr*2 + 1] + b1) * oscale;
                *(unsigned*)(oh + off) = cvt2h(v0, v1);
            }
        }
    }
}

// ---------------------------------------------------------------------------
// Flash attention, fp16 mma, 3-region KV pipeline, base-2 softmax with
// packed fp16 exp (ex2.approx.f16x2) and l computed by a ones-column mma.
// grid=(8,8,4): 256 blocks, 2 sequential Q-chunks per block.
// ---------------------------------------------------------------------------
#define AT_LD 104
#define KV_REG (2*64*AT_LD)

__device__ __forceinline__ void attn_load_kv(__half* Kbuf, size_t gbase, int tid)
{
    __half* Vbuf = Kbuf + 64 * AT_LD;
    #pragma unroll
    for (int j = 0; j < 6; j++) {
        int c = tid + j * 256;
        int arr = (c >= 768) ? 1 : 0;
        int rem = c - arr * 768;
        int row = rem / 12;
        int off = (rem - row * 12) * 8;
        const __half* sp = (arr ? g_Vh : g_Kh) + (gbase + row) * DHH + off;
        __half* dp = (arr ? Vbuf : Kbuf) + row * AT_LD + off;
        CPA(su32(dp), sp);
    }
}

__global__ __launch_bounds__(256, 2) void attn_kernel()
{
    extern __shared__ __half smh[];

    const int b  = blockIdx.z, h = blockIdx.y;
    const int tid = threadIdx.x, wid = tid >> 5, lane = tid & 31;
    const size_t base = ((size_t)(b * HH + h)) * SS;

    const int lrow = lane & 15, lcol8 = (lane >> 4) << 3;
    const int krow_off = (lane & 7) + ((lane & 16) >> 1);
    const int kcol_off = (lane & 8);
    const int NT = SS / 64;   // 32

    // ones-column B fragment for the l-accumulating mma: fp16 1.0 in n=0
    const unsigned bone = ((lane >> 2) == 0) ? 0x3C003C00u : 0u;
    const unsigned bones[2] = { bone, bone };

    __half* R0 = smh;

    for (int qc = 0; qc < 2; qc++) {
        const int s0 = blockIdx.x * 256 + qc * 128;

        {   // load Q chunk into region 0
            int r = tid >> 1, c0 = (tid & 1) * 48;
            size_t go = (base + s0 + r) * DHH + c0;
            __half* dh = R0 + r * AT_LD + c0;
            #pragma unroll
            for (int i = 0; i < 6; i++)
                *(uint4*)(dh + i*8) = *(const uint4*)(g_Qh + go + i*8);
        }

        attn_load_kv(smh + KV_REG,     base, tid);      CP_COMMIT;
        attn_load_kv(smh + 2 * KV_REG, base + 64, tid); CP_COMMIT;

        __syncthreads();   // Q ready
        unsigned qf[6][4];
        {
            int qrow = wid * 16 + lrow;
            #pragma unroll
            for (int dk = 0; dk < 6; dk++)
                ldsm4(qf[dk], su32(R0 + qrow * AT_LD + dk * 16 + lcol8));
        }
        __syncthreads();   // region 0 reusable

        attn_load_kv(R0, base + 128, tid); CP_COMMIT;

        float oacc[12][4];
        #pragma unroll
        for (int j = 0; j < 12; j++)
            #pragma unroll
            for (int t = 0; t < 4; t++) oacc[j][t] = 0.f;
        float lacc[4] = {0.f, 0.f, 0.f, 0.f};   // column 0 tracks l
        float m0r = -1e30f, m1r = -1e30f;

        int cur = 1;
        for (int it = 0; it < NT; it++) {
            if (it < NT - 2)      { CP_WAIT2; }
            else if (it == NT - 2){ CP_WAIT1; }
            else                  { CP_WAIT0; }
            __syncthreads();

            __half* Kp = smh + cur * KV_REG;
            __half* Vp = Kp + 64 * AT_LD;

            // S = Q @ K^T (log2 domain)
            float sacc[8][4];
            #pragma unroll
            for (int j = 0; j < 8; j++)
                #pragma unroll
                for (int t = 0; t < 4; t++) sacc[j][t] = 0.f;

            #pragma unroll
            for (int dk = 0; dk < 6; dk++) {
                int d0 = dk * 16;
                #pragma unroll
                for (int nf2 = 0; nf2 < 4; nf2++) {
                    unsigned bh[4];
                    ldsm4(bh, su32(Kp + (nf2 * 16 + krow_off) * AT_LD + d0 + kcol_off));
                    mma16816(sacc[nf2*2 + 0], qf[dk], bh + 0);
                    mma16816(sacc[nf2*2 + 1], qf[dk], bh + 2);
                }
            }

            // row maxes
            float mx0 = -1e30f, mx1 = -1e30f;
            #pragma unroll
            for (int j = 0; j < 8; j++) {
                mx0 = fmaxf(mx0, fmaxf(sacc[j][0], sacc[j][1]));
                mx1 = fmaxf(mx1, fmaxf(sacc[j][2], sacc[j][3]));
            }
            mx0 = fmaxf(mx0, __shfl_xor_sync(0xffffffffu, mx0, 1));
            mx0 = fmaxf(mx0, __shfl_xor_sync(0xffffffffu, mx0, 2));
            mx1 = fmaxf(mx1, __shfl_xor_sync(0xffffffffu, mx1, 1));
            mx1 = fmaxf(mx1, __shfl_xor_sync(0xffffffffu, mx1, 2));

            // Rescale accumulators (incl. l fragment) only when new row-max.
            if (__any_sync(0xffffffffu, (mx0 > m0r) | (mx1 > m1r))) {
                float mn0 = fmaxf(m0r, mx0), mn1 = fmaxf(m1r, mx1);
                float corr0 = ex2(m0r - mn0), corr1 = ex2(m1r - mn1);
                m0r = mn0; m1r = mn1;
                #pragma unroll
                for (int j = 0; j < 12; j++) {
                    oacc[j][0] *= corr0; oacc[j][1] *= corr0;
                    oacc[j][2] *= corr1; oacc[j][3] *= corr1;
                }
                lacc[0] *= corr0; lacc[1] *= corr0;
                lacc[2] *= corr1; lacc[3] *= corr1;
            }

            // P fragments: fused subtract + packed cvt + packed fp16 exp
            unsigned ph[4][4];
            #pragma unroll
            for (int kf = 0; kf < 4; kf++) {
                #pragma unroll
                for (int q = 0; q < 4; q++) {
                    int fj = kf*2 + (q >> 1);
                    int t0 = (q & 1) * 2;
                    float mr = (t0 == 0) ? m0r : m1r;
                    ph[kf][q] = ex2h2(cvt2h(sacc[fj][t0] - mr, sacc[fj][t0 + 1] - mr));
                }
            }

            // O += P @ V ; l += P @ ones (registers only, no ldsm)
            #pragma unroll
            for (int kf = 0; kf < 4; kf++) {
                int k0 = kf * 16;
                #pragma unroll
                for (int nf2 = 0; nf2 < 6; nf2++) {
                    unsigned bh[4];
                    ldsm4t(bh, su32(Vp + (k0 + lrow) * AT_LD + nf2 * 16 + lcol8));
                    mma16816(oacc[nf2*2 + 0], ph[kf], bh + 0);
                    mma16816(oacc[nf2*2 + 1], ph[kf], bh + 2);
                }
                mma16816(lacc, ph[kf], bones);
            }
            __syncthreads();
            if (it + 3 < NT) {
                attn_load_kv(Kp, base + (size_t)(it + 3) * 64, tid);
                CP_COMMIT;
            }
            cur = (cur == 2) ? 0 : cur + 1;
        }

        // Epilogue: l lives in column 0 (lanes with lane&3==0); broadcast in quad
        float l0 = __shfl_sync(0xffffffffu, lacc[0], lane & ~3);
        float l1 = __shfl_sync(0xffffffffu, lacc[2], lane & ~3);
        float inv0 = 1.0f / l0, inv1 = 1.0f / l1;
        #pragma unroll
        for (int nf = 0; nf < 12; nf++) {
            int col = h * DHH + nf * 8 + (lane & 3) * 2;
            #pragma unroll
            for (int hr = 0; hr < 2; hr++) {
                int s = s0 + wid * 16 + (lane >> 2) + hr * 8;
                size_t off = ((size_t)b * SS + s) * DD + col;
                float inv = hr ? inv1 : inv0;
                *(unsigned*)(g_cath + off) =
                    cvt2h(oacc[nf][hr*2 + 0] * inv, oacc[nf][hr*2 + 1] * inv);
            }
        }
        __syncthreads();   // drain before next chunk reuses regions
    }
}

// ---------------------------------------------------------------------------
// Output projection (fp16): out = cath @ Woh + bo. BM=128, BN=128, BK=64.
// ---------------------------------------------------------------------------
#define OP_LDA 72
#define OP_LDB 136

__device__ __forceinline__ void oproj_load(
    __half* Ah, __half* Bh, int p, int m0, int n0b, int kt, int tid)
{
    #pragma unroll
    for (int j = 0; j < 8; j++) {
        int c = tid + j * 256;
        if (c < 1024) {
            int row = c >> 3, off = (c & 7) * 8;
            CPA(su32(Ah + p * (128*OP_LDA) + row * OP_LDA + off),
                g_cath + (size_t)(m0 + row) * DD + kt + off);
        } else {
            int c2 = c - 1024;
            int row = c2 >> 4, off = (c2 & 15) * 8;
            CPA(su32(Bh + p * (64*OP_LDB) + row * OP_LDB + off),
                g_Woh + (size_t)(kt + row) * DD + n0b + off);
        }
    }
}

__global__ __launch_bounds__(256, 2) void oproj_kernel(
    const float* __restrict__ bo, float* __restrict__ out)
{
    extern __shared__ __half smo[];
    __half* Ah = smo;
    __half* Bh = Ah + 2*128*OP_LDA;

    const int m0  = blockIdx.x * 128;
    const int n0b = blockIdx.y * 128;
    const int tid = threadIdx.x, wid = tid >> 5, lane = tid & 31;
    const int wm = wid >> 1, wn = wid & 1;

    float acc[2][8][4];
    #pragma unroll
    for (int i = 0; i < 2; i++)
        #pragma unroll
        for (int j = 0; j < 8; j++)
            #pragma unroll
            for (int k = 0; k < 4; k++) acc[i][j][k] = 0.f;

    const int lrow = lane & 15, lcol8 = (lane >> 4) << 3;

    oproj_load(Ah, Bh, 0, m0, n0b, 0, tid);
    CP_COMMIT;

    const int NT = DD / 64;
    for (int it = 0; it < NT; it++) {
        int p = it & 1;
        if (it + 1 < NT) {
            oproj_load(Ah, Bh, (it+1)&1, m0, n0b, (it+1)*64, tid);
            CP_COMMIT;
            CP_WAIT1;
        } else {
            CP_WAIT0;
        }
        __syncthreads();

        __half* Ahp = Ah + p * (128*OP_LDA);
        __half* Bhp = Bh + p * (64*OP_LDB);

        #pragma unroll
        for (int ks = 0; ks < 4; ks++) {
            int k0 = ks * 16;
            unsigned ah[2][4];
            #pragma unroll
            for (int mf = 0; mf < 2; mf++) {
                int row = wm * 32 + mf * 16 + lrow;
                ldsm4(ah[mf], su32(Ahp + row * OP_LDA + k0 + lcol8));
            }
            #pragma unroll
            for (int nf2 = 0; nf2 < 4; nf2++) {
                unsigned bh[4];
                int n0 = wn * 64 + nf2 * 16;
                ldsm4t(bh, su32(Bhp + (k0 + lrow) * OP_LDB + n0 + lcol8));
                #pragma unroll
                for (int hn = 0; hn < 2; hn++) {
                    #pragma unroll
                    for (int mf = 0; mf < 2; mf++)
                        mma16816(acc[mf][nf2*2 + hn], ah[mf], bh + hn*2);
                }
            }
        }
        __syncthreads();
    }

    #pragma unroll
    for (int mf = 0; mf < 2; mf++) {
        #pragma unroll
        for (int nf = 0; nf < 8; nf++) {
            int col = n0b + wn * 64 + nf * 8 + (lane & 3) * 2;
            float b0 = bo[col], b1 = bo[col + 1];
            #pragma unroll
            for (int hr = 0; hr < 2; hr++) {
                int m = m0 + wm * 32 + mf * 16 + (lane >> 2) + hr * 8;
                float2 v = make_float2(acc[mf][nf][hr*2+0] + b0,
                                       acc[mf][nf][hr*2+1] + b1);
                *(float2*)(out + (size_t)m * DD + col) = v;
            }
        }
    }
}

// ---------------------------------------------------------------------------
extern "C" void kernel_launch(void* const* d_in, const int* in_sizes, int n_in,
                              void* d_out, int out_size)
{
    (void)in_sizes; (void)n_in; (void)out_size;
    const float* Xq = (const float*)d_in[0];
    const float* Xk = (const float*)d_in[1];
    const float* Xv = (const float*)d_in[2];
    const float* Wq = (const float*)d_in[3];
    const float* bq = (const float*)d_in[4];
    const float* Wk = (const float*)d_in[5];
    const float* bk = (const float*)d_in[6];
    const float* Wv = (const float*)d_in[7];
    const float* bv = (const float*)d_in[8];
    const float* Wo = (const float*)d_in[9];
    const float* bo = (const float*)d_in[10];
    float* out = (float*)d_out;

    const int total4 = 3*NX4 + 4*NW4;
    convert_all<<<(total4 + 255) / 256, 256>>>(Xq, Xk, Xv, Wq, Wk, Wv, Wo);

    const int smem_qkv = (2*128*QK_LDA + 2*64*QK_LDB) * (int)sizeof(__half);   // 63488
    cudaFuncSetAttribute(qkv_kernel, cudaFuncAttributeMaxDynamicSharedMemorySize, smem_qkv);
    dim3 gq(MM / 128, HH, 3);
    qkv_kernel<<<gq, 256, smem_qkv>>>(bq, bk, bv);

    const int smem_attn = 3 * KV_REG * (int)sizeof(__half);                    // 79872
    cudaFuncSetAttribute(attn_kernel, cudaFuncAttributeMaxDynamicSharedMemorySize, smem_attn);
    dim3 ga(SS / 256, HH, BB);
    attn_kernel<<<ga, 256, smem_attn>>>();

    const int smem_op = (2*128*OP_LDA + 2*64*OP_LDB) * (int)sizeof(__half);    // 71680
    cudaFuncSetAttribute(oproj_kernel, cudaFuncAttributeMaxDynamicSharedMemorySize, smem_op);
    dim3 go(MM / 128, DD / 128);
    oproj_kernel<<<go, 256, smem_op>>>(bo, out);
}